// round 5
// baseline (speedup 1.0000x reference)
#include <cuda_runtime.h>
#include <cstdint>
#include <cstddef>

#define NN 100000
#define EE 1600000
#define DD 64
#define GG 512

static constexpr int TILE  = 128;          // edges per tile
static constexpr int NTILE = EE / TILE;    // 12500 exact
static constexpr int SROW  = 132;          // padded row stride (floats) for dup'd tiles
static constexpr size_t SMEM_BYTES =
    (size_t)(2 * 128 * SROW + 2 * 64 * 64) * 4 + (size_t)2 * TILE * 4;  // 168960 B

typedef unsigned long long ull;

// ---------------- device scratch (no runtime allocation allowed) ----------------
__device__ float g_agg[(size_t)NN * DD];                 // 25.6 MB
__device__ float g_sum[GG], g_ss[GG], g_cnt[GG];
__device__ float g_mean[GG], g_rstd[GG];

// ---------------- helpers ----------------
__device__ __forceinline__ ull fma2(ull a, ull b, ull c) {
    ull d;
    asm("fma.rn.f32x2 %0, %1, %2, %3;" : "=l"(d) : "l"(a), "l"(b), "l"(c));
    return d;
}
__device__ __forceinline__ ull pk2(float a, float b) {
    ull r;
    asm("mov.b64 %0, {%1, %2};" : "=l"(r) : "f"(a), "f"(b));
    return r;
}
__device__ __forceinline__ void upk(ull v, float& a, float& b) {
    asm("mov.b64 {%0, %1}, %2;" : "=f"(a), "=f"(b) : "l"(v));
}
__device__ __forceinline__ float silu_f(float v) {
    // x * sigmoid(x) = x / (1 + e^-x). __expf(-x)->inf for very negative x
    // gives __fdividef -> 0, the correct limit.
    return __fdividef(v, 1.0f + __expf(-v));
}

// 64x64 GEMM over a 128-edge tile.
// A pre-duplicated as f32x2 in smem: row i holds dup(A[i][k]) at float offset 2k,
// row stride SROW, XOR-4 swizzle on odd rows. B plain [k][j], stride 64 floats.
// Thread (tx,ty): rows i = 8*ty..8*ty+7, cols j = 4*tx..4*tx+3 as two f32x2 accs.
__device__ __forceinline__ void gemm64(const float* __restrict__ sAdup,
                                       const float* __restrict__ sB,
                                       int tx, int ty, ull acc0[8], ull acc1[8]) {
    const ulonglong2* Bp = (const ulonglong2*)sB;   // 16 x 16B per 64-float row
    const float* arow = sAdup + (8 * ty) * SROW;
#pragma unroll 8
    for (int kk = 0; kk < 32; ++kk) {               // 2 k-values per iteration
        const ulonglong2 b0 = Bp[(2 * kk) * 16 + tx];        // W[2kk  ][4tx..4tx+3]
        const ulonglong2 b1 = Bp[(2 * kk) * 16 + 16 + tx];   // W[2kk+1][4tx..4tx+3]
        const int oE = 4 * kk;
        const int oO = oE ^ 4;                       // swizzled offset, odd rows
#pragma unroll
        for (int ii = 0; ii < 8; ++ii) {
            const ulonglong2 a =
                *(const ulonglong2*)(arow + ii * SROW + ((ii & 1) ? oO : oE));
            // a.x = dup(A[i][2kk]), a.y = dup(A[i][2kk+1])
            acc0[ii] = fma2(a.x, b0.x, acc0[ii]);
            acc1[ii] = fma2(a.x, b0.y, acc1[ii]);
            acc0[ii] = fma2(a.y, b1.x, acc0[ii]);
            acc1[ii] = fma2(a.y, b1.y, acc1[ii]);
        }
    }
}

// ---------------- kernel 1: agg = (1+eps)*x ; zero per-graph stats ----------------
__global__ void init_kernel(const float* __restrict__ x, const float* __restrict__ eps2) {
    const float s = 1.0f + eps2[0];
    const float4* x4 = (const float4*)x;
    float4* a4 = (float4*)g_agg;
    const int total = NN * (DD / 4);
    for (int i = blockIdx.x * blockDim.x + threadIdx.x; i < total;
         i += gridDim.x * blockDim.x) {
        const float4 v = x4[i];
        a4[i] = make_float4(s * v.x, s * v.y, s * v.z, s * v.w);
    }
    if (blockIdx.x == 0) {
        for (int t = threadIdx.x; t < GG; t += blockDim.x) {
            g_sum[t] = 0.0f; g_ss[t] = 0.0f; g_cnt[t] = 0.0f;
        }
    }
}

// ---------------- kernel 2: persistent per-edge GINE conv (live branch only) ----
__global__ void __launch_bounds__(256, 1)
edge_kernel(const float* __restrict__ x, const int* __restrict__ eidx,
            const float* __restrict__ eattr,
            const float* __restrict__ We, const float* __restrict__ be,
            const float* __restrict__ Wm, const float* __restrict__ bm) {
    extern __shared__ float smem[];
    float* sA  = smem;                       // 128 x SROW (edge_attr, dup'd f32x2)
    float* sT  = smem + 128 * SROW;          // 128 x SROW (relu(x_src+silu(ea)), dup'd)
    float* sWe = smem + 2 * 128 * SROW;      // 64 x 64
    float* sWm = sWe + 64 * 64;              // 64 x 64
    int* s_src = (int*)(sWm + 64 * 64);      // 128
    int* s_dst = s_src + TILE;               // 128

    const int tid = threadIdx.x;
    const int tx = tid & 15;                 // j-tile (4 cols)
    const int ty = tid >> 4;                 // i-tile (8 rows)

    {   // stage weights once (persistent CTA)
        const float4* W4 = (const float4*)We;
        const float4* M4 = (const float4*)Wm;
        float4* a4 = (float4*)sWe;
        float4* b4 = (float4*)sWm;
#pragma unroll
        for (int q = 0; q < 4; ++q) {
            a4[tid + 256 * q] = W4[tid + 256 * q];
            b4[tid + 256 * q] = M4[tid + 256 * q];
        }
    }
    const float4 beR = ((const float4*)be)[tx];
    const float4 bmR = ((const float4*)bm)[tx];

    for (int tile = blockIdx.x; tile < NTILE; tile += gridDim.x) {
        const int e0 = tile * TILE;

        // ---- stage: edge indices + edge_attr tile (dup'd, swizzled) ----
        if (tid < TILE) s_src[tid] = eidx[e0 + tid];
        else            s_dst[tid - TILE] = eidx[EE + e0 + (tid - TILE)];

        const float4* EA4 = (const float4*)eattr + (size_t)e0 * 16;
#pragma unroll
        for (int q = 0; q < 8; ++q) {
            const int f = tid + 256 * q;     // flat float4 index, coalesced
            const float4 v = EA4[f];
            const int i = f >> 4, kq = f & 15;
            const int sw = (i & 1) << 2;
            float* r = sA + i * SROW;
            *(float4*)(r + ((8 * kq) ^ sw))     = make_float4(v.x, v.x, v.y, v.y);
            *(float4*)(r + ((8 * kq + 4) ^ sw)) = make_float4(v.z, v.z, v.w, v.w);
        }
        __syncthreads();   // barrier A

        // gather x[src] (overlaps with GEMM1 latency)
        int si[8], di[8];
#pragma unroll
        for (int ii = 0; ii < 8; ++ii) {
            si[ii] = s_src[8 * ty + ii];
            di[ii] = s_dst[8 * ty + ii];
        }
        float4 xg[8];
#pragma unroll
        for (int ii = 0; ii < 8; ++ii)
            xg[ii] = *((const float4*)(x + (size_t)si[ii] * DD) + tx);

        // ---- GEMM1: ea = edge_attr @ We + be ----
        ull acc0[8], acc1[8];
        {
            const ull b0 = pk2(beR.x, beR.y), b1 = pk2(beR.z, beR.w);
#pragma unroll
            for (int ii = 0; ii < 8; ++ii) { acc0[ii] = b0; acc1[ii] = b1; }
        }
        gemm64(sA, sWe, tx, ty, acc0, acc1);

        // ---- epilogue1: t = relu(x_src + silu(ea)), dup-store into sT ----
#pragma unroll
        for (int ii = 0; ii < 8; ++ii) {
            float u0, u1, u2, u3;
            upk(acc0[ii], u0, u1);
            upk(acc1[ii], u2, u3);
            u0 = silu_f(u0); u1 = silu_f(u1); u2 = silu_f(u2); u3 = silu_f(u3);
            const float t0 = fmaxf(xg[ii].x + u0, 0.0f);
            const float t1 = fmaxf(xg[ii].y + u1, 0.0f);
            const float t2 = fmaxf(xg[ii].z + u2, 0.0f);
            const float t3 = fmaxf(xg[ii].w + u3, 0.0f);
            const int sw = ((8 * ty + ii) & 1) << 2;
            float* r = sT + (8 * ty + ii) * SROW;
            *(float4*)(r + ((8 * tx) ^ sw))     = make_float4(t0, t0, t1, t1);
            *(float4*)(r + ((8 * tx + 4) ^ sw)) = make_float4(t2, t2, t3, t3);
        }
        __syncthreads();   // barrier B

        // ---- GEMM2: msg = t @ Wm + bm ----
        {
            const ull b0 = pk2(bmR.x, bmR.y), b1 = pk2(bmR.z, bmR.w);
#pragma unroll
            for (int ii = 0; ii < 8; ++ii) { acc0[ii] = b0; acc1[ii] = b1; }
        }
        gemm64(sT, sWm, tx, ty, acc0, acc1);

        // ---- epilogue2: silu + vector scatter-add into agg[dst] ----
#pragma unroll
        for (int ii = 0; ii < 8; ++ii) {
            float m0, m1, m2, m3;
            upk(acc0[ii], m0, m1);
            upk(acc1[ii], m2, m3);
            m0 = silu_f(m0); m1 = silu_f(m1); m2 = silu_f(m2); m3 = silu_f(m3);
            float* p = g_agg + (size_t)di[ii] * DD + 4 * tx;
            asm volatile("red.global.add.v4.f32 [%0], {%1,%2,%3,%4};"
                         :: "l"(p), "f"(m0), "f"(m1), "f"(m2), "f"(m3) : "memory");
        }
        // No tail barrier needed: barrier A of the next iteration orders the
        // sA/s_src/s_dst overwrites against this iteration's last readers.
    }
}

// ---------------- kernel 3: per-graph sum / sumsq / count ----------------
__global__ void stats_kernel(const int* __restrict__ n2g) {
    const int lane = threadIdx.x & 31;
    const int wid  = (blockIdx.x * blockDim.x + threadIdx.x) >> 5;
    const int nwarps = (gridDim.x * blockDim.x) >> 5;
    for (int n = wid; n < NN; n += nwarps) {
        const float2 v = *(const float2*)(g_agg + (size_t)n * DD + lane * 2);
        float s = v.x + v.y;
        float q = v.x * v.x + v.y * v.y;
#pragma unroll
        for (int o = 16; o; o >>= 1) {
            s += __shfl_xor_sync(0xffffffffu, s, o);
            q += __shfl_xor_sync(0xffffffffu, q, o);
        }
        if (lane == 0) {
            const int g = n2g[n];
            atomicAdd(&g_sum[g], s);
            atomicAdd(&g_ss[g], q);
            atomicAdd(&g_cnt[g], 1.0f);
        }
    }
}

// ---------------- kernel 4: per-graph mean / rstd ----------------
__global__ void finalize_kernel() {
    const int t = threadIdx.x;
    if (t < GG) {
        const float c = fmaxf(g_cnt[t] * (float)DD, 1.0f);
        const float m = g_sum[t] / c;
        const float var = g_ss[t] / c - m * m;
        g_mean[t] = m;
        g_rstd[t] = rsqrtf(var + 1e-5f);
    }
}

// ---------------- kernel 5: normalize + affine + residual + relu ----------------
__global__ void norm_kernel(const float* __restrict__ x, const int* __restrict__ n2g,
                            const float* __restrict__ gamma, const float* __restrict__ beta,
                            float* __restrict__ out) {
    const float4* x4 = (const float4*)x;
    const float4* a4 = (const float4*)g_agg;
    const float4* g4 = (const float4*)gamma;
    const float4* b4 = (const float4*)beta;
    float4* o4 = (float4*)out;
    const int total = NN * (DD / 4);
    for (int i = blockIdx.x * blockDim.x + threadIdx.x; i < total;
         i += gridDim.x * blockDim.x) {
        const int n = i >> 4, c = i & 15;
        const int g = n2g[n];
        const float m = g_mean[g], r = g_rstd[g];
        const float4 a = a4[i], xv = x4[i], gm = g4[c], bt = b4[c];
        float4 o;
        o.x = fmaxf(fmaf((a.x - m) * r, gm.x, bt.x) + xv.x, 0.0f);
        o.y = fmaxf(fmaf((a.y - m) * r, gm.y, bt.y) + xv.y, 0.0f);
        o.z = fmaxf(fmaf((a.z - m) * r, gm.z, bt.z) + xv.z, 0.0f);
        o.w = fmaxf(fmaf((a.w - m) * r, gm.w, bt.w) + xv.w, 0.0f);
        o4[i] = o;
    }
}

// ---------------- launch ----------------
// Input order (metadata): 0:x 1:edge_index 2:edge_attr 3:node2graph
//   4:We1 5:be1 6:Wm1 7:bm1 8:eps1 9:gamma1 10:beta1
//   11:We2 12:be2 13:Wm2 14:bm2 15:eps2 16:gamma2 17:beta2
extern "C" void kernel_launch(void* const* d_in, const int* in_sizes, int n_in,
                              void* d_out, int out_size) {
    const float* x      = (const float*)d_in[0];
    const int*   eidx   = (const int*)d_in[1];
    const float* eattr  = (const float*)d_in[2];
    const int*   n2g    = (const int*)d_in[3];
    const float* We2    = (const float*)d_in[11];
    const float* be2    = (const float*)d_in[12];
    const float* Wm2    = (const float*)d_in[13];
    const float* bm2    = (const float*)d_in[14];
    const float* eps2   = (const float*)d_in[15];
    const float* gamma2 = (const float*)d_in[16];
    const float* beta2  = (const float*)d_in[17];
    float* out = (float*)d_out;

    static bool attr_done = false;
    if (!attr_done) {
        cudaFuncSetAttribute(edge_kernel,
                             cudaFuncAttributeMaxDynamicSharedMemorySize,
                             (int)SMEM_BYTES);
        attr_done = true;
    }

    init_kernel<<<2048, 256>>>(x, eps2);
    edge_kernel<<<148, 256, SMEM_BYTES>>>(x, eidx, eattr, We2, be2, Wm2, bm2);
    stats_kernel<<<1024, 256>>>(n2g);
    finalize_kernel<<<1, 512>>>();
    norm_kernel<<<2048, 256>>>(x, n2g, gamma2, beta2, out);
}

// round 8
// speedup vs baseline: 2.1782x; 2.1782x over previous
#include <cuda_runtime.h>
#include <cuda_bf16.h>
#include <cstdint>
#include <cstddef>

#define NN 100000
#define EE 1600000
#define DD 64
#define GG 512

static constexpr int TILE  = 128;           // edges per tile
static constexpr int NTILE = EE / TILE;     // 12500 exact
static constexpr int GRID  = 148;

// ---- smem layout (byte offsets) ----
static constexpr int OFF_SRC   = 0;                    // 128 ints
static constexpr int OFF_DST   = 512;                  // 128 ints
static constexpr int OFF_BE    = 1024;                 // 64 f32
static constexpr int OFF_BM    = 1280;                 // 64 f32
static constexpr int OFF_A_HI  = 2048;                 // 128 x 128B bf16 (edge tile hi)
static constexpr int OFF_A_LO  = OFF_A_HI + 16384;     // 128 x 128B bf16 (lo)
static constexpr int OFF_WE_HI = OFF_A_LO + 16384;     // 64 x 128B bf16 (We^T hi)
static constexpr int OFF_WE_LO = OFF_WE_HI + 8192;
static constexpr int OFF_WM_HI = OFF_WE_LO + 8192;
static constexpr int OFF_WM_LO = OFF_WM_HI + 8192;
static constexpr int OFF_SCR   = OFF_WM_LO + 8192;     // 128 x 68 f32 scratch
static constexpr int SCR_STRIDE = 68;                  // floats (272B rows)
static constexpr int SMEM_BYTES = OFF_SCR + 128 * SCR_STRIDE * 4;  // 102400

// ---------------- device scratch ----------------
__device__ float g_agg[(size_t)NN * DD];                 // 25.6 MB
__device__ float g_sum[GG], g_ss[GG], g_cnt[GG];
__device__ float g_mean[GG], g_rstd[GG];

// ---------------- helpers ----------------
__device__ __forceinline__ uint32_t smem_u32(const void* p) {
    uint32_t a;
    asm("{ .reg .u64 t; cvta.to.shared.u64 t, %1; cvt.u32.u64 %0, t; }"
        : "=r"(a) : "l"(p));
    return a;
}
__device__ __forceinline__ float silu_f(float v) {
    return __fdividef(v, 1.0f + __expf(-v));
}
// XOR-swizzled offset for a 128B-row tile: row r, 16B-chunk c (0..7)
__device__ __forceinline__ uint32_t a_off(int r, int c4) {
    // c4 = float4 index within row (0..15) -> byte chunk = c4>>1, half = c4&1
    return (uint32_t)r * 128u
         + (uint32_t)(((((c4 >> 1) ^ (r & 7))) << 4) + ((c4 & 1) << 3));
}
__device__ __forceinline__ uint32_t w_off(int n, int k) {
    return (uint32_t)n * 128u
         + (uint32_t)(((((k >> 3) ^ (n & 7))) << 4) + ((k & 7) << 1));
}
// split float -> bf16 hi + bf16 lo (residual)
__device__ __forceinline__ void split2(float a, float b, uint32_t& hi, uint32_t& lo) {
    __nv_bfloat16 ha = __float2bfloat16_rn(a), hb = __float2bfloat16_rn(b);
    __nv_bfloat16 la = __float2bfloat16_rn(a - __bfloat162float(ha));
    __nv_bfloat16 lb = __float2bfloat16_rn(b - __bfloat162float(hb));
    __nv_bfloat162 h2; h2.x = ha; h2.y = hb;
    __nv_bfloat162 l2; l2.x = la; l2.y = lb;
    hi = *(uint32_t*)&h2;
    lo = *(uint32_t*)&l2;
}

__device__ __forceinline__ void ldm4(uint32_t addr, uint32_t r[4]) {
    asm volatile("ldmatrix.sync.aligned.m8n8.x4.shared.b16 {%0,%1,%2,%3}, [%4];"
                 : "=r"(r[0]), "=r"(r[1]), "=r"(r[2]), "=r"(r[3]) : "r"(addr));
}
__device__ __forceinline__ void mma_bf16(float* c, uint32_t a0, uint32_t a1,
                                         uint32_t a2, uint32_t a3,
                                         uint32_t b0, uint32_t b1) {
    asm volatile(
        "mma.sync.aligned.m16n8k16.row.col.f32.bf16.bf16.f32 "
        "{%0,%1,%2,%3}, {%4,%5,%6,%7}, {%8,%9}, {%0,%1,%2,%3};"
        : "+f"(c[0]), "+f"(c[1]), "+f"(c[2]), "+f"(c[3])
        : "r"(a0), "r"(a1), "r"(a2), "r"(a3), "r"(b0), "r"(b1));
}

// 128x64x64 GEMM on one edge tile: acc += A(hi/lo) @ W(hi/lo), 3-term bf16 split.
// Warp w owns rows 16w..16w+15; acc[nt][0..3] is the m16n8 C fragment for n-tile nt.
__device__ __forceinline__ void run_gemm(uint32_t aHiB, uint32_t aLoB,
                                         uint32_t wHiB, uint32_t wLoB,
                                         int w, int l, float acc[8][4]) {
    const int rowA = 16 * w + (l & 7) + (l & 8);
    const uint32_t aRow = (uint32_t)rowA * 128u;
    const int rA7 = rowA & 7;
    const int chAsel = (l >> 4) & 1;
    const int nB0 = (l & 7) + ((l & 16) >> 1);
    const int chBsel = (l >> 3) & 1;
#pragma unroll
    for (int ks = 0; ks < 4; ++ks) {
        const int chA = 2 * ks + chAsel;
        const uint32_t aOff = aRow + (uint32_t)((chA ^ rA7) << 4);
        uint32_t ah[4], al[4];
        ldm4(aHiB + aOff, ah);
        ldm4(aLoB + aOff, al);
        const int chB = 2 * ks + chBsel;
#pragma unroll
        for (int p = 0; p < 4; ++p) {
            const int nB = nB0 + 16 * p;
            const uint32_t bOff = (uint32_t)nB * 128u
                                + (uint32_t)((chB ^ (nB & 7)) << 4);
            uint32_t bh[4], bl[4];
            ldm4(wHiB + bOff, bh);
            ldm4(wLoB + bOff, bl);
            mma_bf16(acc[2 * p],     ah[0], ah[1], ah[2], ah[3], bh[0], bh[1]);
            mma_bf16(acc[2 * p],     al[0], al[1], al[2], al[3], bh[0], bh[1]);
            mma_bf16(acc[2 * p],     ah[0], ah[1], ah[2], ah[3], bl[0], bl[1]);
            mma_bf16(acc[2 * p + 1], ah[0], ah[1], ah[2], ah[3], bh[2], bh[3]);
            mma_bf16(acc[2 * p + 1], al[0], al[1], al[2], al[3], bh[2], bh[3]);
            mma_bf16(acc[2 * p + 1], ah[0], ah[1], ah[2], ah[3], bl[2], bl[3]);
        }
    }
}

// ---------------- kernel 1: agg = (1+eps)*x ; zero per-graph stats ----------------
__global__ void init_kernel(const float* __restrict__ x, const float* __restrict__ eps2) {
    const float s = 1.0f + eps2[0];
    const float4* x4 = (const float4*)x;
    float4* a4 = (float4*)g_agg;
    const int total = NN * (DD / 4);
    for (int i = blockIdx.x * blockDim.x + threadIdx.x; i < total;
         i += gridDim.x * blockDim.x) {
        const float4 v = x4[i];
        a4[i] = make_float4(s * v.x, s * v.y, s * v.z, s * v.w);
    }
    if (blockIdx.x == 0) {
        for (int t = threadIdx.x; t < GG; t += blockDim.x) {
            g_sum[t] = 0.0f; g_ss[t] = 0.0f; g_cnt[t] = 0.0f;
        }
    }
}

// ---------------- kernel 2: persistent bf16-mma GINE conv ----------------
__global__ void __launch_bounds__(256, 1)
edge_kernel(const float* __restrict__ x, const int* __restrict__ eidx,
            const float* __restrict__ eattr,
            const float* __restrict__ We, const float* __restrict__ be,
            const float* __restrict__ Wm, const float* __restrict__ bm) {
    extern __shared__ char smem[];
    const uint32_t sbase = smem_u32(smem);

    const int tid = threadIdx.x;
    const int w = tid >> 5;
    const int l = tid & 31;
    const int r_ep = tid >> 1;           // epilogue row
    const int h_ep = tid & 1;            // epilogue column half (0/1 -> 32 cols)

    int* s_src = (int*)(smem + OFF_SRC);
    int* s_dst = (int*)(smem + OFF_DST);
    float* sbe = (float*)(smem + OFF_BE);
    float* sbm = (float*)(smem + OFF_BM);
    float* scr = (float*)(smem + OFF_SCR);

    const uint32_t aHiB = sbase + OFF_A_HI;
    const uint32_t aLoB = sbase + OFF_A_LO;
    const uint32_t weHiB = sbase + OFF_WE_HI;
    const uint32_t weLoB = sbase + OFF_WE_LO;
    const uint32_t wmHiB = sbase + OFF_WM_HI;
    const uint32_t wmLoB = sbase + OFF_WM_LO;

    // ---- one-time: transpose + split weights into smem, stage biases ----
    for (int idx = tid; idx < 4096; idx += 256) {
        const int k = idx >> 6, n = idx & 63;
        const float we = We[idx];        // We[k][n]
        const float wm = Wm[idx];
        const uint32_t o = w_off(n, k);
        __nv_bfloat16 hw = __float2bfloat16_rn(we);
        __nv_bfloat16 lw = __float2bfloat16_rn(we - __bfloat162float(hw));
        *(__nv_bfloat16*)(smem + OFF_WE_HI + o) = hw;
        *(__nv_bfloat16*)(smem + OFF_WE_LO + o) = lw;
        hw = __float2bfloat16_rn(wm);
        lw = __float2bfloat16_rn(wm - __bfloat162float(hw));
        *(__nv_bfloat16*)(smem + OFF_WM_HI + o) = hw;
        *(__nv_bfloat16*)(smem + OFF_WM_LO + o) = lw;
    }
    if (tid < 64)       sbe[tid] = be[tid];
    else if (tid < 128) sbm[tid - 64] = bm[tid - 64];
    __syncthreads();

    for (int tile = blockIdx.x; tile < NTILE; tile += gridDim.x) {
        const int e0 = tile * TILE;

        // ---- stage indices + edge_attr tile (bf16 hi/lo, swizzled) ----
        if (tid < 128) s_src[tid] = eidx[e0 + tid];
        else           s_dst[tid - 128] = eidx[EE + e0 + (tid - 128)];
        {
            const float4* ep4 = (const float4*)eattr + (size_t)e0 * 16;
#pragma unroll
            for (int q = 0; q < 8; ++q) {
                const int f = tid + 256 * q;         // coalesced f4 index
                const float4 v = ep4[f];
                const int rr = f >> 4, c4 = f & 15;
                uint32_t h0, l0, h1, l1;
                split2(v.x, v.y, h0, l0);
                split2(v.z, v.w, h1, l1);
                const uint32_t o = a_off(rr, c4);
                *(uint2*)(smem + OFF_A_HI + o) = make_uint2(h0, h1);
                *(uint2*)(smem + OFF_A_LO + o) = make_uint2(l0, l1);
            }
        }
        __syncthreads();   // S1

        const int my_src = s_src[r_ep];
        const int my_dst = s_dst[r_ep];
        // prefetch x[src] (latency hidden by GEMM1)
        float4 xg[8];
        {
            const float4* xp = (const float4*)(x + (size_t)my_src * DD + 32 * h_ep);
#pragma unroll
            for (int q = 0; q < 8; ++q) xg[q] = xp[q];
        }

        // ---- GEMM1: ea = edge_attr @ We + be ----
        float acc[8][4];
#pragma unroll
        for (int nt = 0; nt < 8; ++nt) {
            const float2 bv = *(const float2*)(sbe + 8 * nt + (l & 3) * 2);
            acc[nt][0] = bv.x; acc[nt][1] = bv.y;
            acc[nt][2] = bv.x; acc[nt][3] = bv.y;
        }
        run_gemm(aHiB, aLoB, weHiB, weLoB, w, l, acc);
        {
            const int m = 16 * w + (l >> 2);
            const int nc = (l & 3) * 2;
#pragma unroll
            for (int nt = 0; nt < 8; ++nt) {
                *(float2*)(scr + m * SCR_STRIDE + 8 * nt + nc) =
                    make_float2(acc[nt][0], acc[nt][1]);
                *(float2*)(scr + (m + 8) * SCR_STRIDE + 8 * nt + nc) =
                    make_float2(acc[nt][2], acc[nt][3]);
            }
        }
        __syncthreads();   // S2

        // ---- epilogue1: t = relu(x_src + silu(ea)) -> bf16 hi/lo into A buffers ----
        {
            const float* srow = scr + r_ep * SCR_STRIDE + 32 * h_ep;
#pragma unroll
            for (int q = 0; q < 8; ++q) {
                const float4 s = *(const float4*)(srow + 4 * q);
                const float t0 = fmaxf(xg[q].x + silu_f(s.x), 0.0f);
                const float t1 = fmaxf(xg[q].y + silu_f(s.y), 0.0f);
                const float t2 = fmaxf(xg[q].z + silu_f(s.z), 0.0f);
                const float t3 = fmaxf(xg[q].w + silu_f(s.w), 0.0f);
                uint32_t h0, l0, h1, l1;
                split2(t0, t1, h0, l0);
                split2(t2, t3, h1, l1);
                const uint32_t o = a_off(r_ep, 8 * h_ep + q);
                *(uint2*)(smem + OFF_A_HI + o) = make_uint2(h0, h1);
                *(uint2*)(smem + OFF_A_LO + o) = make_uint2(l0, l1);
            }
        }
        __syncthreads();   // S3

        // ---- GEMM2: msg = t @ Wm + bm ----
#pragma unroll
        for (int nt = 0; nt < 8; ++nt) {
            const float2 bv = *(const float2*)(sbm + 8 * nt + (l & 3) * 2);
            acc[nt][0] = bv.x; acc[nt][1] = bv.y;
            acc[nt][2] = bv.x; acc[nt][3] = bv.y;
        }
        run_gemm(aHiB, aLoB, wmHiB, wmLoB, w, l, acc);
        {
            const int m = 16 * w + (l >> 2);
            const int nc = (l & 3) * 2;
#pragma unroll
            for (int nt = 0; nt < 8; ++nt) {
                *(float2*)(scr + m * SCR_STRIDE + 8 * nt + nc) =
                    make_float2(acc[nt][0], acc[nt][1]);
                *(float2*)(scr + (m + 8) * SCR_STRIDE + 8 * nt + nc) =
                    make_float2(acc[nt][2], acc[nt][3]);
            }
        }
        __syncthreads();   // S4

        // ---- epilogue2: silu + vector scatter-add into agg[dst] ----
        {
            const float* srow = scr + r_ep * SCR_STRIDE + 32 * h_ep;
            float* basep = g_agg + (size_t)my_dst * DD + 32 * h_ep;
#pragma unroll
            for (int q = 0; q < 8; ++q) {
                const float4 s = *(const float4*)(srow + 4 * q);
                const float m0 = silu_f(s.x);
                const float m1 = silu_f(s.y);
                const float m2 = silu_f(s.z);
                const float m3 = silu_f(s.w);
                asm volatile("red.global.add.v4.f32 [%0], {%1,%2,%3,%4};"
                             :: "l"(basep + 4 * q), "f"(m0), "f"(m1), "f"(m2), "f"(m3)
                             : "memory");
            }
        }
        __syncthreads();   // S5: scratch/idx reads done before next stage overwrites
    }
}

// ---------------- kernel 3: per-graph sum / sumsq / count ----------------
__global__ void stats_kernel(const int* __restrict__ n2g) {
    const int lane = threadIdx.x & 31;
    const int wid  = (blockIdx.x * blockDim.x + threadIdx.x) >> 5;
    const int nwarps = (gridDim.x * blockDim.x) >> 5;
    for (int n = wid; n < NN; n += nwarps) {
        const float2 v = *(const float2*)(g_agg + (size_t)n * DD + lane * 2);
        float s = v.x + v.y;
        float q = v.x * v.x + v.y * v.y;
#pragma unroll
        for (int o = 16; o; o >>= 1) {
            s += __shfl_xor_sync(0xffffffffu, s, o);
            q += __shfl_xor_sync(0xffffffffu, q, o);
        }
        if (lane == 0) {
            const int g = n2g[n];
            atomicAdd(&g_sum[g], s);
            atomicAdd(&g_ss[g], q);
            atomicAdd(&g_cnt[g], 1.0f);
        }
    }
}

// ---------------- kernel 4: per-graph mean / rstd ----------------
__global__ void finalize_kernel() {
    const int t = threadIdx.x;
    if (t < GG) {
        const float c = fmaxf(g_cnt[t] * (float)DD, 1.0f);
        const float m = g_sum[t] / c;
        const float var = g_ss[t] / c - m * m;
        g_mean[t] = m;
        g_rstd[t] = rsqrtf(var + 1e-5f);
    }
}

// ---------------- kernel 5: normalize + affine + residual + relu ----------------
__global__ void norm_kernel(const float* __restrict__ x, const int* __restrict__ n2g,
                            const float* __restrict__ gamma, const float* __restrict__ beta,
                            float* __restrict__ out) {
    const float4* x4 = (const float4*)x;
    const float4* a4 = (const float4*)g_agg;
    const float4* g4 = (const float4*)gamma;
    const float4* b4 = (const float4*)beta;
    float4* o4 = (float4*)out;
    const int total = NN * (DD / 4);
    for (int i = blockIdx.x * blockDim.x + threadIdx.x; i < total;
         i += gridDim.x * blockDim.x) {
        const int n = i >> 4, c = i & 15;
        const int g = n2g[n];
        const float m = g_mean[g], r = g_rstd[g];
        const float4 a = a4[i], xv = x4[i], gm = g4[c], bt = b4[c];
        float4 o;
        o.x = fmaxf(fmaf((a.x - m) * r, gm.x, bt.x) + xv.x, 0.0f);
        o.y = fmaxf(fmaf((a.y - m) * r, gm.y, bt.y) + xv.y, 0.0f);
        o.z = fmaxf(fmaf((a.z - m) * r, gm.z, bt.z) + xv.z, 0.0f);
        o.w = fmaxf(fmaf((a.w - m) * r, gm.w, bt.w) + xv.w, 0.0f);
        o4[i] = o;
    }
}

// ---------------- launch ----------------
// Inputs: 0:x 1:edge_index 2:edge_attr 3:node2graph
//   4..10: conv1/norm1 (dead branch)  11:We2 12:be2 13:Wm2 14:bm2 15:eps2 16:gamma2 17:beta2
extern "C" void kernel_launch(void* const* d_in, const int* in_sizes, int n_in,
                              void* d_out, int out_size) {
    const float* x      = (const float*)d_in[0];
    const int*   eidx   = (const int*)d_in[1];
    const float* eattr  = (const float*)d_in[2];
    const int*   n2g    = (const int*)d_in[3];
    const float* We2    = (const float*)d_in[11];
    const float* be2    = (const float*)d_in[12];
    const float* Wm2    = (const float*)d_in[13];
    const float* bm2    = (const float*)d_in[14];
    const float* eps2   = (const float*)d_in[15];
    const float* gamma2 = (const float*)d_in[16];
    const float* beta2  = (const float*)d_in[17];
    float* out = (float*)d_out;

    cudaFuncSetAttribute(edge_kernel,
                         cudaFuncAttributeMaxDynamicSharedMemorySize, SMEM_BYTES);

    init_kernel<<<2048, 256>>>(x, eps2);
    edge_kernel<<<GRID, 256, SMEM_BYTES>>>(x, eidx, eattr, We2, be2, Wm2, bm2);
    stats_kernel<<<1024, 256>>>(n2g);
    finalize_kernel<<<1, 512>>>();
    norm_kernel<<<2048, 256>>>(x, n2g, gamma2, beta2, out);
}

// round 9
// speedup vs baseline: 3.1569x; 1.4493x over previous
#include <cuda_runtime.h>
#include <cuda_bf16.h>
#include <cstdint>
#include <cstddef>

#define NN 100000
#define EE 1600000
#define DD 64
#define GG 512

static constexpr int TILE  = 128;           // edges per tile
static constexpr int NTILE = EE / TILE;     // 12500 exact
static constexpr int GRID  = 296;           // 2 CTAs per SM

// ---- smem layout (byte offsets) ----
static constexpr int OFF_SRC   = 0;                    // 128 ints
static constexpr int OFF_DST   = 512;                  // 128 ints
static constexpr int OFF_BE    = 1024;                 // 64 f32
static constexpr int OFF_BM    = 1280;                 // 64 f32
static constexpr int OFF_A_HI  = 2048;                 // 128 x 128B bf16 (A tile hi)
static constexpr int OFF_A_LO  = OFF_A_HI + 16384;
static constexpr int OFF_T_HI  = OFF_A_LO + 16384;     // 128 x 128B bf16 (T tile hi)
static constexpr int OFF_T_LO  = OFF_T_HI + 16384;
static constexpr int OFF_WE_HI = OFF_T_LO + 16384;     // 64 x 128B bf16 (We^T hi)
static constexpr int OFF_WE_LO = OFF_WE_HI + 8192;
static constexpr int OFF_WM_HI = OFF_WE_LO + 8192;
static constexpr int OFF_WM_LO = OFF_WM_HI + 8192;
static constexpr int SMEM_BYTES = OFF_WM_LO + 8192;    // 100352

// ---------------- device scratch ----------------
__device__ float g_agg[(size_t)NN * DD];                 // 25.6 MB
__device__ float g_sum[GG], g_ss[GG], g_cnt[GG];
__device__ float g_mean[GG], g_rstd[GG];

// ---------------- helpers ----------------
__device__ __forceinline__ float silu_f(float v) {
    return __fdividef(v, 1.0f + __expf(-v));
}
// XOR-swizzled offset for a 128B-row tile: row r, float4-chunk c4 (0..15)
__device__ __forceinline__ uint32_t a_off(int r, int c4) {
    return (uint32_t)r * 128u
         + (uint32_t)(((((c4 >> 1) ^ (r & 7))) << 4) + ((c4 & 1) << 3));
}
__device__ __forceinline__ uint32_t w_off(int n, int k) {
    return (uint32_t)n * 128u
         + (uint32_t)(((((k >> 3) ^ (n & 7))) << 4) + ((k & 7) << 1));
}
// split float -> bf16 hi + bf16 lo (residual), packed bf16x2 pairs
__device__ __forceinline__ void split2(float a, float b, uint32_t& hi, uint32_t& lo) {
    __nv_bfloat16 ha = __float2bfloat16_rn(a), hb = __float2bfloat16_rn(b);
    __nv_bfloat16 la = __float2bfloat16_rn(a - __bfloat162float(ha));
    __nv_bfloat16 lb = __float2bfloat16_rn(b - __bfloat162float(hb));
    __nv_bfloat162 h2; h2.x = ha; h2.y = hb;
    __nv_bfloat162 l2; l2.x = la; l2.y = lb;
    hi = *(uint32_t*)&h2;
    lo = *(uint32_t*)&l2;
}

__device__ __forceinline__ void ldm4(uint32_t addr, uint32_t r[4]) {
    asm volatile("ldmatrix.sync.aligned.m8n8.x4.shared.b16 {%0,%1,%2,%3}, [%4];"
                 : "=r"(r[0]), "=r"(r[1]), "=r"(r[2]), "=r"(r[3]) : "r"(addr));
}
__device__ __forceinline__ void mma_bf16(float* c, uint32_t a0, uint32_t a1,
                                         uint32_t a2, uint32_t a3,
                                         uint32_t b0, uint32_t b1) {
    asm volatile(
        "mma.sync.aligned.m16n8k16.row.col.f32.bf16.bf16.f32 "
        "{%0,%1,%2,%3}, {%4,%5,%6,%7}, {%8,%9}, {%0,%1,%2,%3};"
        : "+f"(c[0]), "+f"(c[1]), "+f"(c[2]), "+f"(c[3])
        : "r"(a0), "r"(a1), "r"(a2), "r"(a3), "r"(b0), "r"(b1));
}

// 128x64x64 GEMM on one edge tile: acc += A(hi/lo) @ W(hi/lo), 3-term bf16 split.
// Warp w owns rows 16w..16w+15; acc[nt][0..3] is the m16n8 C fragment for n-tile nt.
__device__ __forceinline__ void run_gemm(uint32_t aHiB, uint32_t aLoB,
                                         uint32_t wHiB, uint32_t wLoB,
                                         int w, int l, float acc[8][4]) {
    const int rowA = 16 * w + (l & 7) + (l & 8);
    const uint32_t aRow = (uint32_t)rowA * 128u;
    const int rA7 = rowA & 7;
    const int chAsel = (l >> 4) & 1;
    const int nB0 = (l & 7) + ((l & 16) >> 1);
    const int chBsel = (l >> 3) & 1;
#pragma unroll
    for (int ks = 0; ks < 4; ++ks) {
        const int chA = 2 * ks + chAsel;
        const uint32_t aOff = aRow + (uint32_t)((chA ^ rA7) << 4);
        uint32_t ah[4], al[4];
        ldm4(aHiB + aOff, ah);
        ldm4(aLoB + aOff, al);
        const int chB = 2 * ks + chBsel;
#pragma unroll
        for (int p = 0; p < 4; ++p) {
            const int nB = nB0 + 16 * p;
            const uint32_t bOff = (uint32_t)nB * 128u
                                + (uint32_t)((chB ^ (nB & 7)) << 4);
            uint32_t bh[4], bl[4];
            ldm4(wHiB + bOff, bh);
            ldm4(wLoB + bOff, bl);
            mma_bf16(acc[2 * p],     ah[0], ah[1], ah[2], ah[3], bh[0], bh[1]);
            mma_bf16(acc[2 * p],     al[0], al[1], al[2], al[3], bh[0], bh[1]);
            mma_bf16(acc[2 * p],     ah[0], ah[1], ah[2], ah[3], bl[0], bl[1]);
            mma_bf16(acc[2 * p + 1], ah[0], ah[1], ah[2], ah[3], bh[2], bh[3]);
            mma_bf16(acc[2 * p + 1], al[0], al[1], al[2], al[3], bh[2], bh[3]);
            mma_bf16(acc[2 * p + 1], ah[0], ah[1], ah[2], ah[3], bl[2], bl[3]);
        }
    }
}

// ---------------- kernel 1: agg = (1+eps)*x ; zero per-graph stats ----------------
__global__ void init_kernel(const float* __restrict__ x, const float* __restrict__ eps2) {
    const float s = 1.0f + eps2[0];
    const float4* x4 = (const float4*)x;
    float4* a4 = (float4*)g_agg;
    const int total = NN * (DD / 4);
    for (int i = blockIdx.x * blockDim.x + threadIdx.x; i < total;
         i += gridDim.x * blockDim.x) {
        const float4 v = x4[i];
        a4[i] = make_float4(s * v.x, s * v.y, s * v.z, s * v.w);
    }
    if (blockIdx.x == 0) {
        for (int t = threadIdx.x; t < GG; t += blockDim.x) {
            g_sum[t] = 0.0f; g_ss[t] = 0.0f; g_cnt[t] = 0.0f;
        }
    }
}

// ---------------- kernel 2: persistent bf16-mma GINE conv ----------------
__global__ void __launch_bounds__(256, 2)
edge_kernel(const float* __restrict__ x, const int* __restrict__ eidx,
            const float* __restrict__ eattr,
            const float* __restrict__ We, const float* __restrict__ be,
            const float* __restrict__ Wm, const float* __restrict__ bm) {
    extern __shared__ char smem[];
    uint32_t sbase;
    asm("{ .reg .u64 t; cvta.to.shared.u64 t, %1; cvt.u32.u64 %0, t; }"
        : "=r"(sbase) : "l"(smem));

    const int tid = threadIdx.x;
    const int w = tid >> 5;
    const int l = tid & 31;
    const int c = l & 3;                 // fragment column sub-index

    int* s_src = (int*)(smem + OFF_SRC);
    int* s_dst = (int*)(smem + OFF_DST);
    float* sbe = (float*)(smem + OFF_BE);
    float* sbm = (float*)(smem + OFF_BM);

    const uint32_t aHiB = sbase + OFF_A_HI;
    const uint32_t aLoB = sbase + OFF_A_LO;
    const uint32_t tHiB = sbase + OFF_T_HI;
    const uint32_t tLoB = sbase + OFF_T_LO;
    const uint32_t weHiB = sbase + OFF_WE_HI;
    const uint32_t weLoB = sbase + OFF_WE_LO;
    const uint32_t wmHiB = sbase + OFF_WM_HI;
    const uint32_t wmLoB = sbase + OFF_WM_LO;

    // ---- one-time: transpose + split weights into smem, stage biases ----
    for (int idx = tid; idx < 4096; idx += 256) {
        const int k = idx >> 6, n = idx & 63;
        const float we = We[idx];        // We[k][n]
        const float wm = Wm[idx];
        const uint32_t o = w_off(n, k);
        __nv_bfloat16 hw = __float2bfloat16_rn(we);
        __nv_bfloat16 lw = __float2bfloat16_rn(we - __bfloat162float(hw));
        *(__nv_bfloat16*)(smem + OFF_WE_HI + o) = hw;
        *(__nv_bfloat16*)(smem + OFF_WE_LO + o) = lw;
        hw = __float2bfloat16_rn(wm);
        lw = __float2bfloat16_rn(wm - __bfloat162float(hw));
        *(__nv_bfloat16*)(smem + OFF_WM_HI + o) = hw;
        *(__nv_bfloat16*)(smem + OFF_WM_LO + o) = lw;
    }
    if (tid < 64)       sbe[tid] = be[tid];
    else if (tid < 128) sbm[tid - 64] = bm[tid - 64];
    __syncthreads();

    // fragment row base for this thread
    const int m0 = 16 * w + (l >> 2);    // second row is m0 + 8
    const int sw0 = (m0 & 7);            // swizzle key (same for m0 and m0+8)

    // ---- prologue: prefetch tile0 eattr + index into registers ----
    int tile = blockIdx.x;
    float4 vr[8];
    int idxn;
    {
        const float4* ep4 = (const float4*)eattr + (size_t)tile * TILE * 16;
#pragma unroll
        for (int q = 0; q < 8; ++q) vr[q] = ep4[tid + 256 * q];
        idxn = (tid < 128) ? eidx[tile * TILE + tid]
                           : eidx[EE + tile * TILE + (tid - 128)];
    }

    for (; tile < NTILE; tile += GRID) {
        // ---- stage indices + A tile (bf16 hi/lo, swizzled) from registers ----
        if (tid < 128) s_src[tid] = idxn;
        else           s_dst[tid - 128] = idxn;
#pragma unroll
        for (int q = 0; q < 8; ++q) {
            const int f = tid + 256 * q;
            const int rr = f >> 4, c4 = f & 15;
            uint32_t h0, l0, h1, l1;
            split2(vr[q].x, vr[q].y, h0, l0);
            split2(vr[q].z, vr[q].w, h1, l1);
            const uint32_t o = a_off(rr, c4);
            *(uint2*)(smem + OFF_A_HI + o) = make_uint2(h0, h1);
            *(uint2*)(smem + OFF_A_LO + o) = make_uint2(l0, l1);
        }
        __syncthreads();   // S1: A tile + indices visible

        // fragment-layout index fetch + x gather (overlaps GEMM1)
        const int src0 = s_src[m0], src1 = s_src[m0 + 8];
        const int dst0 = s_dst[m0], dst1 = s_dst[m0 + 8];
        float2 xv0[8], xv1[8];
        {
            const float2* xr0 = (const float2*)(x + (size_t)src0 * DD) + c;
            const float2* xr1 = (const float2*)(x + (size_t)src1 * DD) + c;
#pragma unroll
            for (int nt = 0; nt < 8; ++nt) {
                xv0[nt] = xr0[4 * nt];
                xv1[nt] = xr1[4 * nt];
            }
        }

        // ---- GEMM1: ea = edge_attr @ We + be ----
        float acc[8][4];
#pragma unroll
        for (int nt = 0; nt < 8; ++nt) {
            const float2 bv = *(const float2*)(sbe + 8 * nt + 2 * c);
            acc[nt][0] = bv.x; acc[nt][1] = bv.y;
            acc[nt][2] = bv.x; acc[nt][3] = bv.y;
        }
        run_gemm(aHiB, aLoB, weHiB, weLoB, w, l, acc);

        // ---- epilogue1 (fragment-direct): t = relu(x_src + silu(ea)) -> T tile ----
#pragma unroll
        for (int nt = 0; nt < 8; ++nt) {
            const float t0 = fmaxf(xv0[nt].x + silu_f(acc[nt][0]), 0.0f);
            const float t1 = fmaxf(xv0[nt].y + silu_f(acc[nt][1]), 0.0f);
            const float t2 = fmaxf(xv1[nt].x + silu_f(acc[nt][2]), 0.0f);
            const float t3 = fmaxf(xv1[nt].y + silu_f(acc[nt][3]), 0.0f);
            uint32_t h0, l0, h1, l1;
            split2(t0, t1, h0, l0);
            split2(t2, t3, h1, l1);
            const uint32_t o0 = (uint32_t)m0 * 128u + (uint32_t)((nt ^ sw0) << 4) + 4u * c;
            const uint32_t o1 = o0 + 8u * 128u;   // row m0+8, same swizzle key
            *(uint32_t*)(smem + OFF_T_HI + o0) = h0;
            *(uint32_t*)(smem + OFF_T_LO + o0) = l0;
            *(uint32_t*)(smem + OFF_T_HI + o1) = h1;
            *(uint32_t*)(smem + OFF_T_LO + o1) = l1;
        }
        __syncthreads();   // S2: T tile visible

        // prefetch next tile into registers (hidden under GEMM2 + epilogue2)
        const int nt_tile = tile + GRID;
        if (nt_tile < NTILE) {
            const float4* ep4 = (const float4*)eattr + (size_t)nt_tile * TILE * 16;
#pragma unroll
            for (int q = 0; q < 8; ++q) vr[q] = ep4[tid + 256 * q];
            idxn = (tid < 128) ? eidx[nt_tile * TILE + tid]
                               : eidx[EE + nt_tile * TILE + (tid - 128)];
        }

        // ---- GEMM2: msg = t @ Wm + bm ----
#pragma unroll
        for (int nt = 0; nt < 8; ++nt) {
            const float2 bv = *(const float2*)(sbm + 8 * nt + 2 * c);
            acc[nt][0] = bv.x; acc[nt][1] = bv.y;
            acc[nt][2] = bv.x; acc[nt][3] = bv.y;
        }
        run_gemm(tHiB, tLoB, wmHiB, wmLoB, w, l, acc);

        // ---- epilogue2 (fragment-direct): silu + scatter-add into agg[dst] ----
        {
            float* p0 = g_agg + (size_t)dst0 * DD + 2 * c;
            float* p1 = g_agg + (size_t)dst1 * DD + 2 * c;
#pragma unroll
            for (int nt = 0; nt < 8; ++nt) {
                const float a0 = silu_f(acc[nt][0]);
                const float a1 = silu_f(acc[nt][1]);
                const float a2 = silu_f(acc[nt][2]);
                const float a3 = silu_f(acc[nt][3]);
                asm volatile("red.global.add.v2.f32 [%0], {%1,%2};"
                             :: "l"(p0 + 8 * nt), "f"(a0), "f"(a1) : "memory");
                asm volatile("red.global.add.v2.f32 [%0], {%1,%2};"
                             :: "l"(p1 + 8 * nt), "f"(a2), "f"(a3) : "memory");
            }
        }
        // No tail barrier: next iteration's A/idx writes are ordered by S1, and
        // all reads of this tile's A/T/indices completed before S2 / in-registers.
    }
}

// ---------------- kernel 3: per-graph sum / sumsq / count ----------------
__global__ void stats_kernel(const int* __restrict__ n2g) {
    const int lane = threadIdx.x & 31;
    const int wid  = (blockIdx.x * blockDim.x + threadIdx.x) >> 5;
    const int nwarps = (gridDim.x * blockDim.x) >> 5;
    for (int n = wid; n < NN; n += nwarps) {
        const float2 v = *(const float2*)(g_agg + (size_t)n * DD + lane * 2);
        float s = v.x + v.y;
        float q = v.x * v.x + v.y * v.y;
#pragma unroll
        for (int o = 16; o; o >>= 1) {
            s += __shfl_xor_sync(0xffffffffu, s, o);
            q += __shfl_xor_sync(0xffffffffu, q, o);
        }
        if (lane == 0) {
            const int g = n2g[n];
            atomicAdd(&g_sum[g], s);
            atomicAdd(&g_ss[g], q);
            atomicAdd(&g_cnt[g], 1.0f);
        }
    }
}

// ---------------- kernel 4: per-graph mean / rstd ----------------
__global__ void finalize_kernel() {
    const int t = threadIdx.x;
    if (t < GG) {
        const float c = fmaxf(g_cnt[t] * (float)DD, 1.0f);
        const float m = g_sum[t] / c;
        const float var = g_ss[t] / c - m * m;
        g_mean[t] = m;
        g_rstd[t] = rsqrtf(var + 1e-5f);
    }
}

// ---------------- kernel 5: normalize + affine + residual + relu ----------------
__global__ void norm_kernel(const float* __restrict__ x, const int* __restrict__ n2g,
                            const float* __restrict__ gamma, const float* __restrict__ beta,
                            float* __restrict__ out) {
    const float4* x4 = (const float4*)x;
    const float4* a4 = (const float4*)g_agg;
    const float4* g4 = (const float4*)gamma;
    const float4* b4 = (const float4*)beta;
    float4* o4 = (float4*)out;
    const int total = NN * (DD / 4);
    for (int i = blockIdx.x * blockDim.x + threadIdx.x; i < total;
         i += gridDim.x * blockDim.x) {
        const int n = i >> 4, c = i & 15;
        const int g = n2g[n];
        const float m = g_mean[g], r = g_rstd[g];
        const float4 a = a4[i], xv = x4[i], gm = g4[c], bt = b4[c];
        float4 o;
        o.x = fmaxf(fmaf((a.x - m) * r, gm.x, bt.x) + xv.x, 0.0f);
        o.y = fmaxf(fmaf((a.y - m) * r, gm.y, bt.y) + xv.y, 0.0f);
        o.z = fmaxf(fmaf((a.z - m) * r, gm.z, bt.z) + xv.z, 0.0f);
        o.w = fmaxf(fmaf((a.w - m) * r, gm.w, bt.w) + xv.w, 0.0f);
        o4[i] = o;
    }
}

// ---------------- launch ----------------
// Inputs: 0:x 1:edge_index 2:edge_attr 3:node2graph
//   4..10: conv1/norm1 (dead branch)  11:We2 12:be2 13:Wm2 14:bm2 15:eps2 16:gamma2 17:beta2
extern "C" void kernel_launch(void* const* d_in, const int* in_sizes, int n_in,
                              void* d_out, int out_size) {
    const float* x      = (const float*)d_in[0];
    const int*   eidx   = (const int*)d_in[1];
    const float* eattr  = (const float*)d_in[2];
    const int*   n2g    = (const int*)d_in[3];
    const float* We2    = (const float*)d_in[11];
    const float* be2    = (const float*)d_in[12];
    const float* Wm2    = (const float*)d_in[13];
    const float* bm2    = (const float*)d_in[14];
    const float* eps2   = (const float*)d_in[15];
    const float* gamma2 = (const float*)d_in[16];
    const float* beta2  = (const float*)d_in[17];
    float* out = (float*)d_out;

    cudaFuncSetAttribute(edge_kernel,
                         cudaFuncAttributeMaxDynamicSharedMemorySize, SMEM_BYTES);

    init_kernel<<<2048, 256>>>(x, eps2);
    edge_kernel<<<GRID, 256, SMEM_BYTES>>>(x, eidx, eattr, We2, be2, Wm2, bm2);
    stats_kernel<<<1024, 256>>>(n2g);
    finalize_kernel<<<1, 512>>>();
    norm_kernel<<<2048, 256>>>(x, n2g, gamma2, beta2, out);
}

// round 10
// speedup vs baseline: 4.0753x; 1.2909x over previous
#include <cuda_runtime.h>
#include <cuda_fp16.h>
#include <cstdint>
#include <cstddef>

#define NN 100000
#define EE 1600000
#define DD 64
#define GG 512

static constexpr int TILE  = 128;           // edges per tile
static constexpr int NTILE = EE / TILE;     // 12500 exact
static constexpr int GRID  = 296;           // 2 CTAs per SM

// ---- smem layout (byte offsets) ----
static constexpr int OFF_SRC   = 0;                    // 128 ints
static constexpr int OFF_DST   = 512;                  // 128 ints
static constexpr int OFF_BE    = 1024;                 // 64 f32
static constexpr int OFF_BM    = 1280;                 // 64 f32
static constexpr int OFF_A_HI  = 2048;                 // 128 x 128B fp16 (A tile hi)
static constexpr int OFF_A_LO  = OFF_A_HI + 16384;     // 128 x 128B fp16 (A residual)
static constexpr int OFF_T_HI  = OFF_A_LO + 16384;     // 128 x 128B fp16 (T tile hi)
static constexpr int OFF_T_LO  = OFF_T_HI + 16384;
static constexpr int OFF_WE    = OFF_T_LO + 16384;     // 64 x 128B fp16 (We^T)
static constexpr int OFF_WM    = OFF_WE + 8192;        // 64 x 128B fp16 (Wm^T)
static constexpr int SMEM_BYTES = OFF_WM + 8192;       // 83968

// ---------------- device scratch ----------------
__device__ float g_agg[(size_t)NN * DD];                 // 25.6 MB
__device__ float g_sum[GG], g_ss[GG], g_cnt[GG];
__device__ float g_mean[GG], g_rstd[GG];

// ---------------- helpers ----------------
__device__ __forceinline__ float silu_f(float v) {
    return __fdividef(v, 1.0f + __expf(-v));
}
// XOR-swizzled offset for a 128B-row tile: row r, float4-chunk c4 (0..15)
__device__ __forceinline__ uint32_t a_off(int r, int c4) {
    return (uint32_t)r * 128u
         + (uint32_t)(((((c4 >> 1) ^ (r & 7))) << 4) + ((c4 & 1) << 3));
}
__device__ __forceinline__ uint32_t w_off(int n, int k) {
    return (uint32_t)n * 128u
         + (uint32_t)(((((k >> 3) ^ (n & 7))) << 4) + ((k & 7) << 1));
}
// split floats -> fp16 hi pair + fp16 lo (residual) pair, packed
__device__ __forceinline__ void split2h(float a, float b, uint32_t& hi, uint32_t& lo) {
    __half2 h = __floats2half2_rn(a, b);
    const float2 hf = __half22float2(h);
    __half2 l = __floats2half2_rn(a - hf.x, b - hf.y);
    hi = *(uint32_t*)&h;
    lo = *(uint32_t*)&l;
}

__device__ __forceinline__ void ldm4(uint32_t addr, uint32_t r[4]) {
    asm volatile("ldmatrix.sync.aligned.m8n8.x4.shared.b16 {%0,%1,%2,%3}, [%4];"
                 : "=r"(r[0]), "=r"(r[1]), "=r"(r[2]), "=r"(r[3]) : "r"(addr));
}
__device__ __forceinline__ void mma_f16(float* c, const uint32_t a[4],
                                        uint32_t b0, uint32_t b1) {
    asm volatile(
        "mma.sync.aligned.m16n8k16.row.col.f32.f16.f16.f32 "
        "{%0,%1,%2,%3}, {%4,%5,%6,%7}, {%8,%9}, {%0,%1,%2,%3};"
        : "+f"(c[0]), "+f"(c[1]), "+f"(c[2]), "+f"(c[3])
        : "r"(a[0]), "r"(a[1]), "r"(a[2]), "r"(a[3]), "r"(b0), "r"(b1));
}

// 128x64x64 GEMM on one edge tile: acc += (A_hi + A_lo) @ W, 2-term fp16 split.
// Warp w owns rows 16w..16w+15; acc[nt][0..3] is the m16n8 C fragment for n-tile nt.
__device__ __forceinline__ void run_gemm(uint32_t aHiB, uint32_t aLoB, uint32_t wB,
                                         int w, int l, float acc[8][4]) {
    const int rowA = 16 * w + (l & 7) + (l & 8);
    const uint32_t aRow = (uint32_t)rowA * 128u;
    const int rA7 = rowA & 7;
    const int chAsel = (l >> 4) & 1;
    const int nB0 = (l & 7) + ((l & 16) >> 1);
    const int chBsel = (l >> 3) & 1;
#pragma unroll
    for (int ks = 0; ks < 4; ++ks) {
        const int chA = 2 * ks + chAsel;
        const uint32_t aOff = aRow + (uint32_t)((chA ^ rA7) << 4);
        uint32_t ah[4], al[4];
        ldm4(aHiB + aOff, ah);
        ldm4(aLoB + aOff, al);
        const int chB = 2 * ks + chBsel;
#pragma unroll
        for (int p = 0; p < 4; ++p) {
            const int nB = nB0 + 16 * p;
            const uint32_t bOff = (uint32_t)nB * 128u
                                + (uint32_t)((chB ^ (nB & 7)) << 4);
            uint32_t bh[4];
            ldm4(wB + bOff, bh);
            mma_f16(acc[2 * p],     ah, bh[0], bh[1]);
            mma_f16(acc[2 * p],     al, bh[0], bh[1]);
            mma_f16(acc[2 * p + 1], ah, bh[2], bh[3]);
            mma_f16(acc[2 * p + 1], al, bh[2], bh[3]);
        }
    }
}

// ---------------- kernel 1: agg = (1+eps)*x ; zero per-graph stats ----------------
__global__ void init_kernel(const float* __restrict__ x, const float* __restrict__ eps2) {
    const float s = 1.0f + eps2[0];
    const float4* x4 = (const float4*)x;
    float4* a4 = (float4*)g_agg;
    const int total = NN * (DD / 4);
    for (int i = blockIdx.x * blockDim.x + threadIdx.x; i < total;
         i += gridDim.x * blockDim.x) {
        const float4 v = x4[i];
        a4[i] = make_float4(s * v.x, s * v.y, s * v.z, s * v.w);
    }
    if (blockIdx.x == 0) {
        for (int t = threadIdx.x; t < GG; t += blockDim.x) {
            g_sum[t] = 0.0f; g_ss[t] = 0.0f; g_cnt[t] = 0.0f;
        }
    }
}

// ---------------- kernel 2: persistent fp16-mma GINE conv ----------------
__global__ void __launch_bounds__(256, 2)
edge_kernel(const float* __restrict__ x, const int* __restrict__ eidx,
            const float* __restrict__ eattr,
            const float* __restrict__ We, const float* __restrict__ be,
            const float* __restrict__ Wm, const float* __restrict__ bm) {
    extern __shared__ char smem[];
    uint32_t sbase;
    asm("{ .reg .u64 t; cvta.to.shared.u64 t, %1; cvt.u32.u64 %0, t; }"
        : "=r"(sbase) : "l"(smem));

    const int tid = threadIdx.x;
    const int w = tid >> 5;
    const int l = tid & 31;
    const int c = l & 3;                 // fragment column sub-index

    int* s_src = (int*)(smem + OFF_SRC);
    int* s_dst = (int*)(smem + OFF_DST);
    float* sbe = (float*)(smem + OFF_BE);
    float* sbm = (float*)(smem + OFF_BM);

    const uint32_t aHiB = sbase + OFF_A_HI;
    const uint32_t aLoB = sbase + OFF_A_LO;
    const uint32_t tHiB = sbase + OFF_T_HI;
    const uint32_t tLoB = sbase + OFF_T_LO;
    const uint32_t weB  = sbase + OFF_WE;
    const uint32_t wmB  = sbase + OFF_WM;

    // ---- one-time: transpose weights into smem (fp16), stage biases ----
    for (int idx = tid; idx < 4096; idx += 256) {
        const int k = idx >> 6, n = idx & 63;
        const uint32_t o = w_off(n, k);
        *(__half*)(smem + OFF_WE + o) = __float2half_rn(We[idx]);  // We[k][n]
        *(__half*)(smem + OFF_WM + o) = __float2half_rn(Wm[idx]);
    }
    if (tid < 64)       sbe[tid] = be[tid];
    else if (tid < 128) sbm[tid - 64] = bm[tid - 64];
    __syncthreads();

    // fragment row base for this thread
    const int m0 = 16 * w + (l >> 2);    // second row is m0 + 8
    const int sw0 = (m0 & 7);            // swizzle key (same for m0 and m0+8)

    // ---- prologue: prefetch tile0 eattr + index into registers ----
    int tile = blockIdx.x;
    float4 vr[8];
    int idxn;
    {
        const float4* ep4 = (const float4*)eattr + (size_t)tile * TILE * 16;
#pragma unroll
        for (int q = 0; q < 8; ++q) vr[q] = ep4[tid + 256 * q];
        idxn = (tid < 128) ? eidx[tile * TILE + tid]
                           : eidx[EE + tile * TILE + (tid - 128)];
    }

    for (; tile < NTILE; tile += GRID) {
        // ---- stage indices + A tile (fp16 hi/lo, swizzled) from registers ----
        if (tid < 128) s_src[tid] = idxn;
        else           s_dst[tid - 128] = idxn;
#pragma unroll
        for (int q = 0; q < 8; ++q) {
            const int f = tid + 256 * q;
            const int rr = f >> 4, c4 = f & 15;
            uint32_t h0, l0, h1, l1;
            split2h(vr[q].x, vr[q].y, h0, l0);
            split2h(vr[q].z, vr[q].w, h1, l1);
            const uint32_t o = a_off(rr, c4);
            *(uint2*)(smem + OFF_A_HI + o) = make_uint2(h0, h1);
            *(uint2*)(smem + OFF_A_LO + o) = make_uint2(l0, l1);
        }
        __syncthreads();   // S1: A tile + indices visible

        // fragment-layout index fetch + x gather (overlaps GEMM1)
        const int src0 = s_src[m0], src1 = s_src[m0 + 8];
        const int dst0 = s_dst[m0], dst1 = s_dst[m0 + 8];
        float2 xv0[8], xv1[8];
        {
            const float2* xr0 = (const float2*)(x + (size_t)src0 * DD) + c;
            const float2* xr1 = (const float2*)(x + (size_t)src1 * DD) + c;
#pragma unroll
            for (int nt = 0; nt < 8; ++nt) {
                xv0[nt] = xr0[4 * nt];
                xv1[nt] = xr1[4 * nt];
            }
        }

        // ---- GEMM1: ea = edge_attr @ We + be ----
        float acc[8][4];
#pragma unroll
        for (int nt = 0; nt < 8; ++nt) {
            const float2 bv = *(const float2*)(sbe + 8 * nt + 2 * c);
            acc[nt][0] = bv.x; acc[nt][1] = bv.y;
            acc[nt][2] = bv.x; acc[nt][3] = bv.y;
        }
        run_gemm(aHiB, aLoB, weB, w, l, acc);

        // ---- epilogue1 (fragment-direct): t = relu(x_src + silu(ea)) -> T tile ----
#pragma unroll
        for (int nt = 0; nt < 8; ++nt) {
            const float t0 = fmaxf(xv0[nt].x + silu_f(acc[nt][0]), 0.0f);
            const float t1 = fmaxf(xv0[nt].y + silu_f(acc[nt][1]), 0.0f);
            const float t2 = fmaxf(xv1[nt].x + silu_f(acc[nt][2]), 0.0f);
            const float t3 = fmaxf(xv1[nt].y + silu_f(acc[nt][3]), 0.0f);
            uint32_t h0, l0, h1, l1;
            split2h(t0, t1, h0, l0);
            split2h(t2, t3, h1, l1);
            const uint32_t o0 = (uint32_t)m0 * 128u + (uint32_t)((nt ^ sw0) << 4) + 4u * c;
            const uint32_t o1 = o0 + 8u * 128u;   // row m0+8, same swizzle key
            *(uint32_t*)(smem + OFF_T_HI + o0) = h0;
            *(uint32_t*)(smem + OFF_T_LO + o0) = l0;
            *(uint32_t*)(smem + OFF_T_HI + o1) = h1;
            *(uint32_t*)(smem + OFF_T_LO + o1) = l1;
        }
        __syncthreads();   // S2: T tile visible

        // prefetch next tile into registers (hidden under GEMM2 + epilogue2)
        const int nt_tile = tile + GRID;
        if (nt_tile < NTILE) {
            const float4* ep4 = (const float4*)eattr + (size_t)nt_tile * TILE * 16;
#pragma unroll
            for (int q = 0; q < 8; ++q) vr[q] = ep4[tid + 256 * q];
            idxn = (tid < 128) ? eidx[nt_tile * TILE + tid]
                               : eidx[EE + nt_tile * TILE + (tid - 128)];
        }

        // ---- GEMM2: msg = t @ Wm + bm ----
#pragma unroll
        for (int nt = 0; nt < 8; ++nt) {
            const float2 bv = *(const float2*)(sbm + 8 * nt + 2 * c);
            acc[nt][0] = bv.x; acc[nt][1] = bv.y;
            acc[nt][2] = bv.x; acc[nt][3] = bv.y;
        }
        run_gemm(tHiB, tLoB, wmB, w, l, acc);

        // ---- epilogue2 (fragment-direct): silu + scatter-add into agg[dst] ----
        {
            float* p0 = g_agg + (size_t)dst0 * DD + 2 * c;
            float* p1 = g_agg + (size_t)dst1 * DD + 2 * c;
#pragma unroll
            for (int nt = 0; nt < 8; ++nt) {
                const float a0 = silu_f(acc[nt][0]);
                const float a1 = silu_f(acc[nt][1]);
                const float a2 = silu_f(acc[nt][2]);
                const float a3 = silu_f(acc[nt][3]);
                asm volatile("red.global.add.v2.f32 [%0], {%1,%2};"
                             :: "l"(p0 + 8 * nt), "f"(a0), "f"(a1) : "memory");
                asm volatile("red.global.add.v2.f32 [%0], {%1,%2};"
                             :: "l"(p1 + 8 * nt), "f"(a2), "f"(a3) : "memory");
            }
        }
        // No tail barrier: next iteration's A/idx writes are ordered by S1, and
        // all reads of this tile's A/T/indices completed before S2 / in-registers.
    }
}

// ---------------- kernel 3: per-graph sum / sumsq / count ----------------
__global__ void stats_kernel(const int* __restrict__ n2g) {
    const int lane = threadIdx.x & 31;
    const int wid  = (blockIdx.x * blockDim.x + threadIdx.x) >> 5;
    const int nwarps = (gridDim.x * blockDim.x) >> 5;
    for (int n = wid; n < NN; n += nwarps) {
        const float2 v = *(const float2*)(g_agg + (size_t)n * DD + lane * 2);
        float s = v.x + v.y;
        float q = v.x * v.x + v.y * v.y;
#pragma unroll
        for (int o = 16; o; o >>= 1) {
            s += __shfl_xor_sync(0xffffffffu, s, o);
            q += __shfl_xor_sync(0xffffffffu, q, o);
        }
        if (lane == 0) {
            const int g = n2g[n];
            atomicAdd(&g_sum[g], s);
            atomicAdd(&g_ss[g], q);
            atomicAdd(&g_cnt[g], 1.0f);
        }
    }
}

// ---------------- kernel 4: per-graph mean / rstd ----------------
__global__ void finalize_kernel() {
    const int t = threadIdx.x;
    if (t < GG) {
        const float c = fmaxf(g_cnt[t] * (float)DD, 1.0f);
        const float m = g_sum[t] / c;
        const float var = g_ss[t] / c - m * m;
        g_mean[t] = m;
        g_rstd[t] = rsqrtf(var + 1e-5f);
    }
}

// ---------------- kernel 5: normalize + affine + residual + relu ----------------
__global__ void norm_kernel(const float* __restrict__ x, const int* __restrict__ n2g,
                            const float* __restrict__ gamma, const float* __restrict__ beta,
                            float* __restrict__ out) {
    const float4* x4 = (const float4*)x;
    const float4* a4 = (const float4*)g_agg;
    const float4* g4 = (const float4*)gamma;
    const float4* b4 = (const float4*)beta;
    float4* o4 = (float4*)out;
    const int total = NN * (DD / 4);
    for (int i = blockIdx.x * blockDim.x + threadIdx.x; i < total;
         i += gridDim.x * blockDim.x) {
        const int n = i >> 4, c = i & 15;
        const int g = n2g[n];
        const float m = g_mean[g], r = g_rstd[g];
        const float4 a = a4[i], xv = x4[i], gm = g4[c], bt = b4[c];
        float4 o;
        o.x = fmaxf(fmaf((a.x - m) * r, gm.x, bt.x) + xv.x, 0.0f);
        o.y = fmaxf(fmaf((a.y - m) * r, gm.y, bt.y) + xv.y, 0.0f);
        o.z = fmaxf(fmaf((a.z - m) * r, gm.z, bt.z) + xv.z, 0.0f);
        o.w = fmaxf(fmaf((a.w - m) * r, gm.w, bt.w) + xv.w, 0.0f);
        o4[i] = o;
    }
}

// ---------------- launch ----------------
// Inputs: 0:x 1:edge_index 2:edge_attr 3:node2graph
//   4..10: conv1/norm1 (dead branch)  11:We2 12:be2 13:Wm2 14:bm2 15:eps2 16:gamma2 17:beta2
extern "C" void kernel_launch(void* const* d_in, const int* in_sizes, int n_in,
                              void* d_out, int out_size) {
    const float* x      = (const float*)d_in[0];
    const int*   eidx   = (const int*)d_in[1];
    const float* eattr  = (const float*)d_in[2];
    const int*   n2g    = (const int*)d_in[3];
    const float* We2    = (const float*)d_in[11];
    const float* be2    = (const float*)d_in[12];
    const float* Wm2    = (const float*)d_in[13];
    const float* bm2    = (const float*)d_in[14];
    const float* eps2   = (const float*)d_in[15];
    const float* gamma2 = (const float*)d_in[16];
    const float* beta2  = (const float*)d_in[17];
    float* out = (float*)d_out;

    cudaFuncSetAttribute(edge_kernel,
                         cudaFuncAttributeMaxDynamicSharedMemorySize, SMEM_BYTES);

    init_kernel<<<2048, 256>>>(x, eps2);
    edge_kernel<<<GRID, 256, SMEM_BYTES>>>(x, eidx, eattr, We2, be2, Wm2, bm2);
    stats_kernel<<<1024, 256>>>(n2g);
    finalize_kernel<<<1, 512>>>();
    norm_kernel<<<2048, 256>>>(x, n2g, gamma2, beta2, out);
}

// round 12
// speedup vs baseline: 4.4847x; 1.1005x over previous
#include <cuda_runtime.h>
#include <cuda_fp16.h>
#include <cstdint>
#include <cstddef>

#define NN 100000
#define EE 1600000
#define DD 64
#define GG 512

static constexpr int TILE  = 128;           // edges per tile
static constexpr int NTILE = EE / TILE;     // 12500 exact
static constexpr int GRID  = 296;           // 2 CTAs per SM

// ---- smem layout (byte offsets) ----
static constexpr int OFF_SRC   = 0;                    // 128 ints
static constexpr int OFF_DST   = 512;                  // 128 ints
static constexpr int OFF_BE    = 1024;                 // 64 f32
static constexpr int OFF_BM    = 1280;                 // 64 f32
static constexpr int OFF_A     = 2048;                 // 128 x 128B fp16 (A tile)
static constexpr int OFF_T     = OFF_A + 16384;        // 128 x 128B fp16 (T tile)
static constexpr int OFF_WE    = OFF_T + 16384;        // 64 x 128B fp16 (We^T)
static constexpr int OFF_WM    = OFF_WE + 8192;        // 64 x 128B fp16 (Wm^T)
static constexpr int SMEM_BYTES = OFF_WM + 8192;       // 51200

// ---------------- device scratch ----------------
__device__ float g_agg[(size_t)NN * DD];                 // 25.6 MB
__device__ float g_sum[GG], g_ss[GG], g_cnt[GG];
__device__ float g_mean[GG], g_rstd[GG];

// ---------------- helpers ----------------
__device__ __forceinline__ float silu_f(float v) {
    return __fdividef(v, 1.0f + __expf(-v));
}
// XOR-swizzled offset for a 128B-row tile: row r, float4-chunk c4 (0..15)
__device__ __forceinline__ uint32_t a_off(int r, int c4) {
    return (uint32_t)r * 128u
         + (uint32_t)(((((c4 >> 1) ^ (r & 7))) << 4) + ((c4 & 1) << 3));
}
__device__ __forceinline__ uint32_t w_off(int n, int k) {
    return (uint32_t)n * 128u
         + (uint32_t)(((((k >> 3) ^ (n & 7))) << 4) + ((k & 7) << 1));
}
__device__ __forceinline__ uint32_t pack2h(float a, float b) {
    __half2 h = __floats2half2_rn(a, b);
    return *(uint32_t*)&h;
}

__device__ __forceinline__ void ldm4(uint32_t addr, uint32_t r[4]) {
    asm volatile("ldmatrix.sync.aligned.m8n8.x4.shared.b16 {%0,%1,%2,%3}, [%4];"
                 : "=r"(r[0]), "=r"(r[1]), "=r"(r[2]), "=r"(r[3]) : "r"(addr));
}
__device__ __forceinline__ void mma_f16(float* c, const uint32_t a[4],
                                        uint32_t b0, uint32_t b1) {
    asm volatile(
        "mma.sync.aligned.m16n8k16.row.col.f32.f16.f16.f32 "
        "{%0,%1,%2,%3}, {%4,%5,%6,%7}, {%8,%9}, {%0,%1,%2,%3};"
        : "+f"(c[0]), "+f"(c[1]), "+f"(c[2]), "+f"(c[3])
        : "r"(a[0]), "r"(a[1]), "r"(a[2]), "r"(a[3]), "r"(b0), "r"(b1));
}

// 128x64x64 GEMM on one edge tile: acc += A @ W, single-term fp16.
// Warp w owns rows 16w..16w+15; acc[nt][0..3] is the m16n8 C fragment for n-tile nt.
__device__ __forceinline__ void run_gemm(uint32_t aB, uint32_t wB,
                                         int w, int l, float acc[8][4]) {
    const int rowA = 16 * w + (l & 7) + (l & 8);
    const uint32_t aRow = (uint32_t)rowA * 128u;
    const int rA7 = rowA & 7;
    const int chAsel = (l >> 4) & 1;
    const int nB0 = (l & 7) + ((l & 16) >> 1);
    const int chBsel = (l >> 3) & 1;
#pragma unroll
    for (int ks = 0; ks < 4; ++ks) {
        const int chA = 2 * ks + chAsel;
        const uint32_t aOff = aRow + (uint32_t)((chA ^ rA7) << 4);
        uint32_t ah[4];
        ldm4(aB + aOff, ah);
        const int chB = 2 * ks + chBsel;
#pragma unroll
        for (int p = 0; p < 4; ++p) {
            const int nB = nB0 + 16 * p;
            const uint32_t bOff = (uint32_t)nB * 128u
                                + (uint32_t)((chB ^ (nB & 7)) << 4);
            uint32_t bh[4];
            ldm4(wB + bOff, bh);
            mma_f16(acc[2 * p],     ah, bh[0], bh[1]);
            mma_f16(acc[2 * p + 1], ah, bh[2], bh[3]);
        }
    }
}

// ---------------- kernel 1: agg = (1+eps)*x ; zero per-graph stats ----------------
__global__ void init_kernel(const float* __restrict__ x, const float* __restrict__ eps2) {
    const float s = 1.0f + eps2[0];
    const float4* x4 = (const float4*)x;
    float4* a4 = (float4*)g_agg;
    const int total = NN * (DD / 4);
    for (int i = blockIdx.x * blockDim.x + threadIdx.x; i < total;
         i += gridDim.x * blockDim.x) {
        const float4 v = x4[i];
        a4[i] = make_float4(s * v.x, s * v.y, s * v.z, s * v.w);
    }
    if (blockIdx.x == 0) {
        for (int t = threadIdx.x; t < GG; t += blockDim.x) {
            g_sum[t] = 0.0f; g_ss[t] = 0.0f; g_cnt[t] = 0.0f;
        }
    }
}

// ---------------- kernel 2: persistent fp16-mma GINE conv ----------------
__global__ void __launch_bounds__(256, 2)
edge_kernel(const float* __restrict__ x, const int* __restrict__ eidx,
            const float* __restrict__ eattr,
            const float* __restrict__ We, const float* __restrict__ be,
            const float* __restrict__ Wm, const float* __restrict__ bm) {
    extern __shared__ char smem[];
    uint32_t sbase;
    asm("{ .reg .u64 t; cvta.to.shared.u64 t, %1; cvt.u32.u64 %0, t; }"
        : "=r"(sbase) : "l"(smem));

    const int tid = threadIdx.x;
    const int w = tid >> 5;
    const int l = tid & 31;
    const int c = l & 3;                 // fragment column sub-index

    int* s_src = (int*)(smem + OFF_SRC);
    int* s_dst = (int*)(smem + OFF_DST);
    float* sbe = (float*)(smem + OFF_BE);
    float* sbm = (float*)(smem + OFF_BM);

    const uint32_t aB  = sbase + OFF_A;
    const uint32_t tB  = sbase + OFF_T;
    const uint32_t weB = sbase + OFF_WE;
    const uint32_t wmB = sbase + OFF_WM;

    // ---- one-time: transpose weights into smem (fp16), stage biases ----
    for (int idx = tid; idx < 4096; idx += 256) {
        const int k = idx >> 6, n = idx & 63;
        const uint32_t o = w_off(n, k);
        *(__half*)(smem + OFF_WE + o) = __float2half_rn(We[idx]);  // We[k][n]
        *(__half*)(smem + OFF_WM + o) = __float2half_rn(Wm[idx]);
    }
    if (tid < 64)       sbe[tid] = be[tid];
    else if (tid < 128) sbm[tid - 64] = bm[tid - 64];
    __syncthreads();

    // fragment row base for this thread
    const int m0 = 16 * w + (l >> 2);    // second row is m0 + 8
    const int sw0 = (m0 & 7);            // swizzle key (same for m0 and m0+8)

    // ---- prologue: prefetch tile0 eattr + index into registers ----
    int tile = blockIdx.x;
    float4 vr[8];
    int idxn;
    {
        const float4* ep4 = (const float4*)eattr + (size_t)tile * TILE * 16;
#pragma unroll
        for (int q = 0; q < 8; ++q) vr[q] = ep4[tid + 256 * q];
        idxn = (tid < 128) ? eidx[tile * TILE + tid]
                           : eidx[EE + tile * TILE + (tid - 128)];
    }

    for (; tile < NTILE; tile += GRID) {
        // ---- stage indices + A tile (fp16, swizzled) from registers ----
        if (tid < 128) s_src[tid] = idxn;
        else           s_dst[tid - 128] = idxn;
#pragma unroll
        for (int q = 0; q < 8; ++q) {
            const int f = tid + 256 * q;
            const int rr = f >> 4, c4 = f & 15;
            const uint32_t h0 = pack2h(vr[q].x, vr[q].y);
            const uint32_t h1 = pack2h(vr[q].z, vr[q].w);
            *(uint2*)(smem + OFF_A + a_off(rr, c4)) = make_uint2(h0, h1);
        }
        __syncthreads();   // S1: A tile + indices visible

        // fragment-layout index fetch + x gather (overlaps GEMM1)
        const int src0 = s_src[m0], src1 = s_src[m0 + 8];
        const int dst0 = s_dst[m0], dst1 = s_dst[m0 + 8];
        float2 xv0[8], xv1[8];
        {
            const float2* xr0 = (const float2*)(x + (size_t)src0 * DD) + c;
            const float2* xr1 = (const float2*)(x + (size_t)src1 * DD) + c;
#pragma unroll
            for (int nt = 0; nt < 8; ++nt) {
                xv0[nt] = xr0[4 * nt];
                xv1[nt] = xr1[4 * nt];
            }
        }

        // ---- GEMM1: ea = edge_attr @ We + be ----
        float acc[8][4];
#pragma unroll
        for (int nt = 0; nt < 8; ++nt) {
            const float2 bv = *(const float2*)(sbe + 8 * nt + 2 * c);
            acc[nt][0] = bv.x; acc[nt][1] = bv.y;
            acc[nt][2] = bv.x; acc[nt][3] = bv.y;
        }
        run_gemm(aB, weB, w, l, acc);

        // ---- epilogue1 (fragment-direct): t = relu(x_src + silu(ea)) -> T tile ----
#pragma unroll
        for (int nt = 0; nt < 8; ++nt) {
            const float t0 = fmaxf(xv0[nt].x + silu_f(acc[nt][0]), 0.0f);
            const float t1 = fmaxf(xv0[nt].y + silu_f(acc[nt][1]), 0.0f);
            const float t2 = fmaxf(xv1[nt].x + silu_f(acc[nt][2]), 0.0f);
            const float t3 = fmaxf(xv1[nt].y + silu_f(acc[nt][3]), 0.0f);
            const uint32_t o0 = (uint32_t)m0 * 128u + (uint32_t)((nt ^ sw0) << 4) + 4u * c;
            const uint32_t o1 = o0 + 8u * 128u;   // row m0+8, same swizzle key
            *(uint32_t*)(smem + OFF_T + o0) = pack2h(t0, t1);
            *(uint32_t*)(smem + OFF_T + o1) = pack2h(t2, t3);
        }
        __syncthreads();   // S2: T tile visible

        // prefetch next tile into registers (hidden under GEMM2 + epilogue2)
        const int nt_tile = tile + GRID;
        if (nt_tile < NTILE) {
            const float4* ep4 = (const float4*)eattr + (size_t)nt_tile * TILE * 16;
#pragma unroll
            for (int q = 0; q < 8; ++q) vr[q] = ep4[tid + 256 * q];
            idxn = (tid < 128) ? eidx[nt_tile * TILE + tid]
                               : eidx[EE + nt_tile * TILE + (tid - 128)];
        }

        // ---- GEMM2: msg = t @ Wm + bm ----
#pragma unroll
        for (int nt = 0; nt < 8; ++nt) {
            const float2 bv = *(const float2*)(sbm + 8 * nt + 2 * c);
            acc[nt][0] = bv.x; acc[nt][1] = bv.y;
            acc[nt][2] = bv.x; acc[nt][3] = bv.y;
        }
        run_gemm(tB, wmB, w, l, acc);

        // ---- epilogue2 (fragment-direct): silu + scatter-add into agg[dst] ----
        {
            float* p0 = g_agg + (size_t)dst0 * DD + 2 * c;
            float* p1 = g_agg + (size_t)dst1 * DD + 2 * c;
#pragma unroll
            for (int nt = 0; nt < 8; ++nt) {
                const float a0 = silu_f(acc[nt][0]);
                const float a1 = silu_f(acc[nt][1]);
                const float a2 = silu_f(acc[nt][2]);
                const float a3 = silu_f(acc[nt][3]);
                asm volatile("red.global.add.v2.f32 [%0], {%1,%2};"
                             :: "l"(p0 + 8 * nt), "f"(a0), "f"(a1) : "memory");
                asm volatile("red.global.add.v2.f32 [%0], {%1,%2};"
                             :: "l"(p1 + 8 * nt), "f"(a2), "f"(a3) : "memory");
            }
        }
        // No tail barrier: next iteration's A/idx writes are ordered by S1, and
        // all reads of this tile's A/T/indices completed before S2 / in-registers.
    }
}

// ---------------- kernel 3: per-graph sum / sumsq / count ----------------
__global__ void stats_kernel(const int* __restrict__ n2g) {
    const int lane = threadIdx.x & 31;
    const int wid  = (blockIdx.x * blockDim.x + threadIdx.x) >> 5;
    const int nwarps = (gridDim.x * blockDim.x) >> 5;
    for (int n = wid; n < NN; n += nwarps) {
        const float2 v = *(const float2*)(g_agg + (size_t)n * DD + lane * 2);
        float s = v.x + v.y;
        float q = v.x * v.x + v.y * v.y;
#pragma unroll
        for (int o = 16; o; o >>= 1) {
            s += __shfl_xor_sync(0xffffffffu, s, o);
            q += __shfl_xor_sync(0xffffffffu, q, o);
        }
        if (lane == 0) {
            const int g = n2g[n];
            atomicAdd(&g_sum[g], s);
            atomicAdd(&g_ss[g], q);
            atomicAdd(&g_cnt[g], 1.0f);
        }
    }
}

// ---------------- kernel 4: per-graph mean / rstd ----------------
__global__ void finalize_kernel() {
    const int t = threadIdx.x;
    if (t < GG) {
        const float c = fmaxf(g_cnt[t] * (float)DD, 1.0f);
        const float m = g_sum[t] / c;
        const float var = g_ss[t] / c - m * m;
        g_mean[t] = m;
        g_rstd[t] = rsqrtf(var + 1e-5f);
    }
}

// ---------------- kernel 5: normalize + affine + residual + relu ----------------
__global__ void norm_kernel(const float* __restrict__ x, const int* __restrict__ n2g,
                            const float* __restrict__ gamma, const float* __restrict__ beta,
                            float* __restrict__ out) {
    const float4* x4 = (const float4*)x;
    const float4* a4 = (const float4*)g_agg;
    const float4* g4 = (const float4*)gamma;
    const float4* b4 = (const float4*)beta;
    float4* o4 = (float4*)out;
    const int total = NN * (DD / 4);
    for (int i = blockIdx.x * blockDim.x + threadIdx.x; i < total;
         i += gridDim.x * blockDim.x) {
        const int n = i >> 4, c = i & 15;
        const int g = n2g[n];
        const float m = g_mean[g], r = g_rstd[g];
        const float4 a = a4[i], xv = x4[i], gm = g4[c], bt = b4[c];
        float4 o;
        o.x = fmaxf(fmaf((a.x - m) * r, gm.x, bt.x) + xv.x, 0.0f);
        o.y = fmaxf(fmaf((a.y - m) * r, gm.y, bt.y) + xv.y, 0.0f);
        o.z = fmaxf(fmaf((a.z - m) * r, gm.z, bt.z) + xv.z, 0.0f);
        o.w = fmaxf(fmaf((a.w - m) * r, gm.w, bt.w) + xv.w, 0.0f);
        o4[i] = o;
    }
}

// ---------------- launch ----------------
// Inputs: 0:x 1:edge_index 2:edge_attr 3:node2graph
//   4..10: conv1/norm1 (dead branch)  11:We2 12:be2 13:Wm2 14:bm2 15:eps2 16:gamma2 17:beta2
extern "C" void kernel_launch(void* const* d_in, const int* in_sizes, int n_in,
                              void* d_out, int out_size) {
    const float* x      = (const float*)d_in[0];
    const int*   eidx   = (const int*)d_in[1];
    const float* eattr  = (const float*)d_in[2];
    const int*   n2g    = (const int*)d_in[3];
    const float* We2    = (const float*)d_in[11];
    const float* be2    = (const float*)d_in[12];
    const float* Wm2    = (const float*)d_in[13];
    const float* bm2    = (const float*)d_in[14];
    const float* eps2   = (const float*)d_in[15];
    const float* gamma2 = (const float*)d_in[16];
    const float* beta2  = (const float*)d_in[17];
    float* out = (float*)d_out;

    cudaFuncSetAttribute(edge_kernel,
                         cudaFuncAttributeMaxDynamicSharedMemorySize, SMEM_BYTES);

    init_kernel<<<2048, 256>>>(x, eps2);
    edge_kernel<<<GRID, 256, SMEM_BYTES>>>(x, eidx, eattr, We2, be2, Wm2, bm2);
    stats_kernel<<<1024, 256>>>(n2g);
    finalize_kernel<<<1, 512>>>();
    norm_kernel<<<2048, 256>>>(x, n2g, gamma2, beta2, out);
}

// round 13
// speedup vs baseline: 4.6357x; 1.0337x over previous
#include <cuda_runtime.h>
#include <cuda_fp16.h>
#include <cstdint>
#include <cstddef>

#define NN 100000
#define EE 1600000
#define DD 64
#define GG 512

static constexpr int TILE  = 128;           // edges per tile
static constexpr int NTILE = EE / TILE;     // 12500 exact
static constexpr int GRID  = 296;           // 2 CTAs per SM

// ---- smem layout (byte offsets) ----
static constexpr int OFF_SRC   = 0;                    // 128 ints
static constexpr int OFF_DST   = 512;                  // 128 ints
static constexpr int OFF_BE    = 1024;                 // 64 f32
static constexpr int OFF_BM    = 1280;                 // 64 f32
static constexpr int OFF_A     = 2048;                 // 128 x 128B fp16 (A tile)
static constexpr int OFF_T     = OFF_A + 16384;        // 128 x 128B fp16 (T tile)
static constexpr int OFF_WE    = OFF_T + 16384;        // 64 x 128B fp16 (We^T)
static constexpr int OFF_WM    = OFF_WE + 8192;        // 64 x 128B fp16 (Wm^T)
static constexpr int SMEM_BYTES = OFF_WM + 8192;       // 51200

// ---------------- device scratch ----------------
__device__ float g_agg[(size_t)NN * DD];                 // 25.6 MB
__device__ float g_sum[GG], g_ss[GG], g_cnt[GG];
__device__ float g_mean[GG], g_rstd[GG];

// ---------------- helpers ----------------
__device__ __forceinline__ float silu_f(float v) {
    return __fdividef(v, 1.0f + __expf(-v));
}
// half2 silu via tanh.approx.f16x2: silu(x) = (x/2)*tanh(x/2) + (x/2)
__device__ __forceinline__ __half2 silu_h2(__half2 h) {
    const __half2 half_c = __floats2half2_rn(0.5f, 0.5f);
    __half2 hh = __hmul2(h, half_c);
    uint32_t ti, to;
    ti = *(uint32_t*)&hh;
    asm("tanh.approx.f16x2 %0, %1;" : "=r"(to) : "r"(ti));
    __half2 th = *(__half2*)&to;
    return __hfma2(hh, th, hh);
}
// XOR-swizzled offset for a 128B-row tile: row r, float4-chunk c4 (0..15)
__device__ __forceinline__ uint32_t a_off(int r, int c4) {
    return (uint32_t)r * 128u
         + (uint32_t)(((((c4 >> 1) ^ (r & 7))) << 4) + ((c4 & 1) << 3));
}
__device__ __forceinline__ uint32_t w_off(int n, int k) {
    return (uint32_t)n * 128u
         + (uint32_t)(((((k >> 3) ^ (n & 7))) << 4) + ((k & 7) << 1));
}
__device__ __forceinline__ uint32_t pack2h(float a, float b) {
    __half2 h = __floats2half2_rn(a, b);
    return *(uint32_t*)&h;
}

__device__ __forceinline__ void ldm4(uint32_t addr, uint32_t r[4]) {
    asm volatile("ldmatrix.sync.aligned.m8n8.x4.shared.b16 {%0,%1,%2,%3}, [%4];"
                 : "=r"(r[0]), "=r"(r[1]), "=r"(r[2]), "=r"(r[3]) : "r"(addr));
}
__device__ __forceinline__ void mma_f16(float* c, const uint32_t a[4],
                                        uint32_t b0, uint32_t b1) {
    asm volatile(
        "mma.sync.aligned.m16n8k16.row.col.f32.f16.f16.f32 "
        "{%0,%1,%2,%3}, {%4,%5,%6,%7}, {%8,%9}, {%0,%1,%2,%3};"
        : "+f"(c[0]), "+f"(c[1]), "+f"(c[2]), "+f"(c[3])
        : "r"(a[0]), "r"(a[1]), "r"(a[2]), "r"(a[3]), "r"(b0), "r"(b1));
}

// 128x64x64 GEMM on one edge tile: acc += A @ W, single-term fp16.
// Warp w owns rows 16w..16w+15; acc[nt][0..3] is the m16n8 C fragment for n-tile nt.
__device__ __forceinline__ void run_gemm(uint32_t aB, uint32_t wB,
                                         int w, int l, float acc[8][4]) {
    const int rowA = 16 * w + (l & 7) + (l & 8);
    const uint32_t aRow = (uint32_t)rowA * 128u;
    const int rA7 = rowA & 7;
    const int chAsel = (l >> 4) & 1;
    const int nB0 = (l & 7) + ((l & 16) >> 1);
    const int chBsel = (l >> 3) & 1;
#pragma unroll
    for (int ks = 0; ks < 4; ++ks) {
        const int chA = 2 * ks + chAsel;
        const uint32_t aOff = aRow + (uint32_t)((chA ^ rA7) << 4);
        uint32_t ah[4];
        ldm4(aB + aOff, ah);
        const int chB = 2 * ks + chBsel;
#pragma unroll
        for (int p = 0; p < 4; ++p) {
            const int nB = nB0 + 16 * p;
            const uint32_t bOff = (uint32_t)nB * 128u
                                + (uint32_t)((chB ^ (nB & 7)) << 4);
            uint32_t bh[4];
            ldm4(wB + bOff, bh);
            mma_f16(acc[2 * p],     ah, bh[0], bh[1]);
            mma_f16(acc[2 * p + 1], ah, bh[2], bh[3]);
        }
    }
}

// ---------------- kernel 1: agg = (1+eps)*x ; zero per-graph stats ----------------
__global__ void init_kernel(const float* __restrict__ x, const float* __restrict__ eps2) {
    const float s = 1.0f + eps2[0];
    const float4* x4 = (const float4*)x;
    float4* a4 = (float4*)g_agg;
    const int total = NN * (DD / 4);
    for (int i = blockIdx.x * blockDim.x + threadIdx.x; i < total;
         i += gridDim.x * blockDim.x) {
        const float4 v = x4[i];
        a4[i] = make_float4(s * v.x, s * v.y, s * v.z, s * v.w);
    }
    if (blockIdx.x == 0) {
        for (int t = threadIdx.x; t < GG; t += blockDim.x) {
            g_sum[t] = 0.0f; g_ss[t] = 0.0f; g_cnt[t] = 0.0f;
        }
    }
}

// ---------------- kernel 2: persistent fp16-mma GINE conv ----------------
__global__ void __launch_bounds__(256, 2)
edge_kernel(const float* __restrict__ x, const int* __restrict__ eidx,
            const float* __restrict__ eattr,
            const float* __restrict__ We, const float* __restrict__ be,
            const float* __restrict__ Wm, const float* __restrict__ bm) {
    extern __shared__ char smem[];
    uint32_t sbase;
    asm("{ .reg .u64 t; cvta.to.shared.u64 t, %1; cvt.u32.u64 %0, t; }"
        : "=r"(sbase) : "l"(smem));

    const int tid = threadIdx.x;
    const int w = tid >> 5;
    const int l = tid & 31;
    const int c = l & 3;                 // fragment column sub-index

    int* s_src = (int*)(smem + OFF_SRC);
    int* s_dst = (int*)(smem + OFF_DST);
    float* sbe = (float*)(smem + OFF_BE);
    float* sbm = (float*)(smem + OFF_BM);

    const uint32_t aB  = sbase + OFF_A;
    const uint32_t tB  = sbase + OFF_T;
    const uint32_t weB = sbase + OFF_WE;
    const uint32_t wmB = sbase + OFF_WM;

    // ---- one-time: transpose weights into smem (fp16), stage biases ----
    for (int idx = tid; idx < 4096; idx += 256) {
        const int k = idx >> 6, n = idx & 63;
        const uint32_t o = w_off(n, k);
        *(__half*)(smem + OFF_WE + o) = __float2half_rn(We[idx]);  // We[k][n]
        *(__half*)(smem + OFF_WM + o) = __float2half_rn(Wm[idx]);
    }
    if (tid < 64)       sbe[tid] = be[tid];
    else if (tid < 128) sbm[tid - 64] = bm[tid - 64];
    __syncthreads();

    // fragment row base for this thread
    const int m0 = 16 * w + (l >> 2);    // second row is m0 + 8
    const int sw0 = (m0 & 7);            // swizzle key (same for m0 and m0+8)
    const __half2 zero_h2 = __floats2half2_rn(0.0f, 0.0f);

    // ---- prologue: prefetch tile0 eattr + index into registers ----
    int tile = blockIdx.x;
    float4 vr[8];
    int idxn;
    {
        const float4* ep4 = (const float4*)eattr + (size_t)tile * TILE * 16;
#pragma unroll
        for (int q = 0; q < 8; ++q) vr[q] = ep4[tid + 256 * q];
        idxn = (tid < 128) ? eidx[tile * TILE + tid]
                           : eidx[EE + tile * TILE + (tid - 128)];
    }

    for (; tile < NTILE; tile += GRID) {
        // ---- stage indices + A tile (fp16, swizzled) from registers ----
        if (tid < 128) s_src[tid] = idxn;
        else           s_dst[tid - 128] = idxn;
#pragma unroll
        for (int q = 0; q < 8; ++q) {
            const int f = tid + 256 * q;
            const int rr = f >> 4, c4 = f & 15;
            const uint32_t h0 = pack2h(vr[q].x, vr[q].y);
            const uint32_t h1 = pack2h(vr[q].z, vr[q].w);
            *(uint2*)(smem + OFF_A + a_off(rr, c4)) = make_uint2(h0, h1);
        }
        __syncthreads();   // S1: A tile + indices visible

        // fragment-layout index fetch + x gather (overlaps GEMM1)
        const int src0 = s_src[m0], src1 = s_src[m0 + 8];
        const int dst0 = s_dst[m0], dst1 = s_dst[m0 + 8];
        float2 xv0[8], xv1[8];
        {
            const float2* xr0 = (const float2*)(x + (size_t)src0 * DD) + c;
            const float2* xr1 = (const float2*)(x + (size_t)src1 * DD) + c;
#pragma unroll
            for (int nt = 0; nt < 8; ++nt) {
                xv0[nt] = xr0[4 * nt];
                xv1[nt] = xr1[4 * nt];
            }
        }

        // ---- GEMM1: ea = edge_attr @ We + be ----
        float acc[8][4];
#pragma unroll
        for (int nt = 0; nt < 8; ++nt) {
            const float2 bv = *(const float2*)(sbe + 8 * nt + 2 * c);
            acc[nt][0] = bv.x; acc[nt][1] = bv.y;
            acc[nt][2] = bv.x; acc[nt][3] = bv.y;
        }
        run_gemm(aB, weB, w, l, acc);

        // ---- epilogue1 (half2): t = relu(x_src + silu(ea)) -> T tile ----
#pragma unroll
        for (int nt = 0; nt < 8; ++nt) {
            const __half2 s0 = silu_h2(__floats2half2_rn(acc[nt][0], acc[nt][1]));
            const __half2 s1 = silu_h2(__floats2half2_rn(acc[nt][2], acc[nt][3]));
            const __half2 x0 = __floats2half2_rn(xv0[nt].x, xv0[nt].y);
            const __half2 x1 = __floats2half2_rn(xv1[nt].x, xv1[nt].y);
            const __half2 t0 = __hmax2(__hadd2(x0, s0), zero_h2);
            const __half2 t1 = __hmax2(__hadd2(x1, s1), zero_h2);
            const uint32_t o0 = (uint32_t)m0 * 128u + (uint32_t)((nt ^ sw0) << 4) + 4u * c;
            const uint32_t o1 = o0 + 8u * 128u;   // row m0+8, same swizzle key
            *(uint32_t*)(smem + OFF_T + o0) = *(const uint32_t*)&t0;
            *(uint32_t*)(smem + OFF_T + o1) = *(const uint32_t*)&t1;
        }
        __syncthreads();   // S2: T tile visible

        // prefetch next tile into registers (hidden under GEMM2 + epilogue2)
        const int nt_tile = tile + GRID;
        if (nt_tile < NTILE) {
            const float4* ep4 = (const float4*)eattr + (size_t)nt_tile * TILE * 16;
#pragma unroll
            for (int q = 0; q < 8; ++q) vr[q] = ep4[tid + 256 * q];
            idxn = (tid < 128) ? eidx[nt_tile * TILE + tid]
                               : eidx[EE + nt_tile * TILE + (tid - 128)];
        }

        // ---- GEMM2: msg = t @ Wm + bm ----
#pragma unroll
        for (int nt = 0; nt < 8; ++nt) {
            const float2 bv = *(const float2*)(sbm + 8 * nt + 2 * c);
            acc[nt][0] = bv.x; acc[nt][1] = bv.y;
            acc[nt][2] = bv.x; acc[nt][3] = bv.y;
        }
        run_gemm(tB, wmB, w, l, acc);

        // ---- epilogue2 (half2 silu): scatter-add into agg[dst] ----
        {
            float* p0 = g_agg + (size_t)dst0 * DD + 2 * c;
            float* p1 = g_agg + (size_t)dst1 * DD + 2 * c;
#pragma unroll
            for (int nt = 0; nt < 8; ++nt) {
                const __half2 s0 = silu_h2(__floats2half2_rn(acc[nt][0], acc[nt][1]));
                const __half2 s1 = silu_h2(__floats2half2_rn(acc[nt][2], acc[nt][3]));
                const float2 m01 = __half22float2(s0);
                const float2 m23 = __half22float2(s1);
                asm volatile("red.global.add.v2.f32 [%0], {%1,%2};"
                             :: "l"(p0 + 8 * nt), "f"(m01.x), "f"(m01.y) : "memory");
                asm volatile("red.global.add.v2.f32 [%0], {%1,%2};"
                             :: "l"(p1 + 8 * nt), "f"(m23.x), "f"(m23.y) : "memory");
            }
        }
        // No tail barrier: next iteration's A/idx writes are ordered by S1, and
        // all reads of this tile's A/T/indices completed before S2 / in-registers.
    }
}

// ---------------- kernel 3: per-graph sum / sumsq / count ----------------
__global__ void stats_kernel(const int* __restrict__ n2g) {
    const int lane = threadIdx.x & 31;
    const int wid  = (blockIdx.x * blockDim.x + threadIdx.x) >> 5;
    const int nwarps = (gridDim.x * blockDim.x) >> 5;
    for (int n = wid; n < NN; n += nwarps) {
        const float2 v = *(const float2*)(g_agg + (size_t)n * DD + lane * 2);
        float s = v.x + v.y;
        float q = v.x * v.x + v.y * v.y;
#pragma unroll
        for (int o = 16; o; o >>= 1) {
            s += __shfl_xor_sync(0xffffffffu, s, o);
            q += __shfl_xor_sync(0xffffffffu, q, o);
        }
        if (lane == 0) {
            const int g = n2g[n];
            atomicAdd(&g_sum[g], s);
            atomicAdd(&g_ss[g], q);
            atomicAdd(&g_cnt[g], 1.0f);
        }
    }
}

// ---------------- kernel 4: per-graph mean / rstd ----------------
__global__ void finalize_kernel() {
    const int t = threadIdx.x;
    if (t < GG) {
        const float c = fmaxf(g_cnt[t] * (float)DD, 1.0f);
        const float m = g_sum[t] / c;
        const float var = g_ss[t] / c - m * m;
        g_mean[t] = m;
        g_rstd[t] = rsqrtf(var + 1e-5f);
    }
}

// ---------------- kernel 5: normalize + affine + residual + relu ----------------
__global__ void norm_kernel(const float* __restrict__ x, const int* __restrict__ n2g,
                            const float* __restrict__ gamma, const float* __restrict__ beta,
                            float* __restrict__ out) {
    const float4* x4 = (const float4*)x;
    const float4* a4 = (const float4*)g_agg;
    const float4* g4 = (const float4*)gamma;
    const float4* b4 = (const float4*)beta;
    float4* o4 = (float4*)out;
    const int total = NN * (DD / 4);
    for (int i = blockIdx.x * blockDim.x + threadIdx.x; i < total;
         i += gridDim.x * blockDim.x) {
        const int n = i >> 4, c = i & 15;
        const int g = n2g[n];
        const float m = g_mean[g], r = g_rstd[g];
        const float4 a = a4[i], xv = x4[i], gm = g4[c], bt = b4[c];
        float4 o;
        o.x = fmaxf(fmaf((a.x - m) * r, gm.x, bt.x) + xv.x, 0.0f);
        o.y = fmaxf(fmaf((a.y - m) * r, gm.y, bt.y) + xv.y, 0.0f);
        o.z = fmaxf(fmaf((a.z - m) * r, gm.z, bt.z) + xv.z, 0.0f);
        o.w = fmaxf(fmaf((a.w - m) * r, gm.w, bt.w) + xv.w, 0.0f);
        o4[i] = o;
    }
}

// ---------------- launch ----------------
// Inputs: 0:x 1:edge_index 2:edge_attr 3:node2graph
//   4..10: conv1/norm1 (dead branch)  11:We2 12:be2 13:Wm2 14:bm2 15:eps2 16:gamma2 17:beta2
extern "C" void kernel_launch(void* const* d_in, const int* in_sizes, int n_in,
                              void* d_out, int out_size) {
    const float* x      = (const float*)d_in[0];
    const int*   eidx   = (const int*)d_in[1];
    const float* eattr  = (const float*)d_in[2];
    const int*   n2g    = (const int*)d_in[3];
    const float* We2    = (const float*)d_in[11];
    const float* be2    = (const float*)d_in[12];
    const float* Wm2    = (const float*)d_in[13];
    const float* bm2    = (const float*)d_in[14];
    const float* eps2   = (const float*)d_in[15];
    const float* gamma2 = (const float*)d_in[16];
    const float* beta2  = (const float*)d_in[17];
    float* out = (float*)d_out;

    cudaFuncSetAttribute(edge_kernel,
                         cudaFuncAttributeMaxDynamicSharedMemorySize, SMEM_BYTES);

    init_kernel<<<2048, 256>>>(x, eps2);
    edge_kernel<<<GRID, 256, SMEM_BYTES>>>(x, eidx, eattr, We2, be2, Wm2, bm2);
    stats_kernel<<<1024, 256>>>(n2g);
    finalize_kernel<<<1, 512>>>();
    norm_kernel<<<2048, 256>>>(x, n2g, gamma2, beta2, out);
}

// round 14
// speedup vs baseline: 4.6862x; 1.0109x over previous
#include <cuda_runtime.h>
#include <cuda_fp16.h>
#include <cstdint>
#include <cstddef>

#define NN 100000
#define EE 1600000
#define DD 64
#define GG 512

static constexpr int TILE  = 128;           // edges per tile
static constexpr int NTILE = EE / TILE;     // 12500 exact
static constexpr int GRID  = 296;           // 2 CTAs per SM

// ---- smem layout (byte offsets) ----
static constexpr int OFF_SRC   = 0;                    // 128 ints
static constexpr int OFF_DST   = 512;                  // 128 ints
static constexpr int OFF_BE    = 1024;                 // 64 f32
static constexpr int OFF_BM    = 1280;                 // 64 f32
static constexpr int OFF_A     = 2048;                 // 128 x 128B fp16 (A tile)
static constexpr int OFF_T     = OFF_A + 16384;        // 128 x 128B fp16 (T tile)
static constexpr int OFF_WE    = OFF_T + 16384;        // 64 x 128B fp16 (We^T)
static constexpr int OFF_WM    = OFF_WE + 8192;        // 64 x 128B fp16 (Wm^T)
static constexpr int SMEM_BYTES = OFF_WM + 8192;       // 51200

// ---------------- device scratch ----------------
__device__ float g_agg[(size_t)NN * DD];                 // 25.6 MB
__device__ float g_sum[GG], g_ss[GG], g_cnt[GG];
__device__ float g_mean[GG], g_rstd[GG];

// ---------------- helpers ----------------
// half2 silu via tanh.approx.f16x2: silu(x) = (x/2)*tanh(x/2) + (x/2)
__device__ __forceinline__ __half2 silu_h2(__half2 h) {
    const __half2 half_c = __floats2half2_rn(0.5f, 0.5f);
    __half2 hh = __hmul2(h, half_c);
    uint32_t ti, to;
    ti = *(uint32_t*)&hh;
    asm("tanh.approx.f16x2 %0, %1;" : "=r"(to) : "r"(ti));
    __half2 th = *(__half2*)&to;
    return __hfma2(hh, th, hh);
}
// XOR-swizzled offset for a 128B-row tile: row r, float4-chunk c4 (0..15)
__device__ __forceinline__ uint32_t a_off(int r, int c4) {
    return (uint32_t)r * 128u
         + (uint32_t)(((((c4 >> 1) ^ (r & 7))) << 4) + ((c4 & 1) << 3));
}
__device__ __forceinline__ uint32_t w_off(int n, int k) {
    return (uint32_t)n * 128u
         + (uint32_t)(((((k >> 3) ^ (n & 7))) << 4) + ((k & 7) << 1));
}
__device__ __forceinline__ uint32_t pack2h(float a, float b) {
    __half2 h = __floats2half2_rn(a, b);
    return *(uint32_t*)&h;
}

__device__ __forceinline__ void ldm4(uint32_t addr, uint32_t r[4]) {
    asm volatile("ldmatrix.sync.aligned.m8n8.x4.shared.b16 {%0,%1,%2,%3}, [%4];"
                 : "=r"(r[0]), "=r"(r[1]), "=r"(r[2]), "=r"(r[3]) : "r"(addr));
}
__device__ __forceinline__ void mma_f16(float* c, const uint32_t a[4],
                                        uint32_t b0, uint32_t b1) {
    asm volatile(
        "mma.sync.aligned.m16n8k16.row.col.f32.f16.f16.f32 "
        "{%0,%1,%2,%3}, {%4,%5,%6,%7}, {%8,%9}, {%0,%1,%2,%3};"
        : "+f"(c[0]), "+f"(c[1]), "+f"(c[2]), "+f"(c[3])
        : "r"(a[0]), "r"(a[1]), "r"(a[2]), "r"(a[3]), "r"(b0), "r"(b1));
}

// 128x64x64 GEMM on one edge tile: acc += A @ W, single-term fp16.
// Warp w owns rows 16w..16w+15; acc[nt][0..3] is the m16n8 C fragment for n-tile nt.
__device__ __forceinline__ void run_gemm(uint32_t aB, uint32_t wB,
                                         int w, int l, float acc[8][4]) {
    const int rowA = 16 * w + (l & 7) + (l & 8);
    const uint32_t aRow = (uint32_t)rowA * 128u;
    const int rA7 = rowA & 7;
    const int chAsel = (l >> 4) & 1;
    const int nB0 = (l & 7) + ((l & 16) >> 1);
    const int chBsel = (l >> 3) & 1;
#pragma unroll
    for (int ks = 0; ks < 4; ++ks) {
        const int chA = 2 * ks + chAsel;
        const uint32_t aOff = aRow + (uint32_t)((chA ^ rA7) << 4);
        uint32_t ah[4];
        ldm4(aB + aOff, ah);
        const int chB = 2 * ks + chBsel;
#pragma unroll
        for (int p = 0; p < 4; ++p) {
            const int nB = nB0 + 16 * p;
            const uint32_t bOff = (uint32_t)nB * 128u
                                + (uint32_t)((chB ^ (nB & 7)) << 4);
            uint32_t bh[4];
            ldm4(wB + bOff, bh);
            mma_f16(acc[2 * p],     ah, bh[0], bh[1]);
            mma_f16(acc[2 * p + 1], ah, bh[2], bh[3]);
        }
    }
}

// ---------------- no-op kernel (shifts the ncu -s slot onto edge_kernel) --------
__global__ void nop_kernel() {}

// ---------------- kernel 1: agg = (1+eps)*x ; zero per-graph stats ----------------
// (also pre-warms x and agg into L2, which edge_kernel relies on staying resident)
__global__ void init_kernel(const float* __restrict__ x, const float* __restrict__ eps2) {
    const float s = 1.0f + eps2[0];
    const float4* x4 = (const float4*)x;
    float4* a4 = (float4*)g_agg;
    const int total = NN * (DD / 4);
    for (int i = blockIdx.x * blockDim.x + threadIdx.x; i < total;
         i += gridDim.x * blockDim.x) {
        const float4 v = x4[i];
        a4[i] = make_float4(s * v.x, s * v.y, s * v.z, s * v.w);
    }
    if (blockIdx.x == 0) {
        for (int t = threadIdx.x; t < GG; t += blockDim.x) {
            g_sum[t] = 0.0f; g_ss[t] = 0.0f; g_cnt[t] = 0.0f;
        }
    }
}

// ---------------- kernel 2: persistent fp16-mma GINE conv ----------------
__global__ void __launch_bounds__(256, 2)
edge_kernel(const float* __restrict__ x, const int* __restrict__ eidx,
            const float* __restrict__ eattr,
            const float* __restrict__ We, const float* __restrict__ be,
            const float* __restrict__ Wm, const float* __restrict__ bm) {
    extern __shared__ char smem[];
    uint32_t sbase;
    asm("{ .reg .u64 t; cvta.to.shared.u64 t, %1; cvt.u32.u64 %0, t; }"
        : "=r"(sbase) : "l"(smem));

    const int tid = threadIdx.x;
    const int w = tid >> 5;
    const int l = tid & 31;
    const int c = l & 3;                 // fragment column sub-index

    int* s_src = (int*)(smem + OFF_SRC);
    int* s_dst = (int*)(smem + OFF_DST);
    float* sbe = (float*)(smem + OFF_BE);
    float* sbm = (float*)(smem + OFF_BM);

    const uint32_t aB  = sbase + OFF_A;
    const uint32_t tB  = sbase + OFF_T;
    const uint32_t weB = sbase + OFF_WE;
    const uint32_t wmB = sbase + OFF_WM;

    // ---- one-time: transpose weights into smem (fp16), stage biases ----
    for (int idx = tid; idx < 4096; idx += 256) {
        const int k = idx >> 6, n = idx & 63;
        const uint32_t o = w_off(n, k);
        *(__half*)(smem + OFF_WE + o) = __float2half_rn(We[idx]);  // We[k][n]
        *(__half*)(smem + OFF_WM + o) = __float2half_rn(Wm[idx]);
    }
    if (tid < 64)       sbe[tid] = be[tid];
    else if (tid < 128) sbm[tid - 64] = bm[tid - 64];
    __syncthreads();

    // fragment row base for this thread
    const int m0 = 16 * w + (l >> 2);    // second row is m0 + 8
    const int sw0 = (m0 & 7);            // swizzle key (same for m0 and m0+8)
    const __half2 zero_h2 = __floats2half2_rn(0.0f, 0.0f);

    // ---- prologue: prefetch tile0 eattr (streaming) + index into registers ----
    int tile = blockIdx.x;
    float4 vr[8];
    int idxn;
    {
        const float4* ep4 = (const float4*)eattr + (size_t)tile * TILE * 16;
#pragma unroll
        for (int q = 0; q < 8; ++q) vr[q] = __ldcs(ep4 + tid + 256 * q);
        idxn = (tid < 128) ? eidx[tile * TILE + tid]
                           : eidx[EE + tile * TILE + (tid - 128)];
    }

    for (; tile < NTILE; tile += GRID) {
        // ---- stage indices + A tile (fp16, swizzled) from registers ----
        if (tid < 128) s_src[tid] = idxn;
        else           s_dst[tid - 128] = idxn;
#pragma unroll
        for (int q = 0; q < 8; ++q) {
            const int f = tid + 256 * q;
            const int rr = f >> 4, c4 = f & 15;
            const uint32_t h0 = pack2h(vr[q].x, vr[q].y);
            const uint32_t h1 = pack2h(vr[q].z, vr[q].w);
            *(uint2*)(smem + OFF_A + a_off(rr, c4)) = make_uint2(h0, h1);
        }
        __syncthreads();   // S1: A tile + indices visible

        // fragment-layout index fetch + x gather (overlaps GEMM1; x is L2-resident)
        const int src0 = s_src[m0], src1 = s_src[m0 + 8];
        const int dst0 = s_dst[m0], dst1 = s_dst[m0 + 8];
        float2 xv0[8], xv1[8];
        {
            const float2* xr0 = (const float2*)(x + (size_t)src0 * DD) + c;
            const float2* xr1 = (const float2*)(x + (size_t)src1 * DD) + c;
#pragma unroll
            for (int nt = 0; nt < 8; ++nt) {
                xv0[nt] = xr0[4 * nt];
                xv1[nt] = xr1[4 * nt];
            }
        }

        // ---- GEMM1: ea = edge_attr @ We + be ----
        float acc[8][4];
#pragma unroll
        for (int nt = 0; nt < 8; ++nt) {
            const float2 bv = *(const float2*)(sbe + 8 * nt + 2 * c);
            acc[nt][0] = bv.x; acc[nt][1] = bv.y;
            acc[nt][2] = bv.x; acc[nt][3] = bv.y;
        }
        run_gemm(aB, weB, w, l, acc);

        // ---- epilogue1 (half2): t = relu(x_src + silu(ea)) -> T tile ----
#pragma unroll
        for (int nt = 0; nt < 8; ++nt) {
            const __half2 s0 = silu_h2(__floats2half2_rn(acc[nt][0], acc[nt][1]));
            const __half2 s1 = silu_h2(__floats2half2_rn(acc[nt][2], acc[nt][3]));
            const __half2 x0 = __floats2half2_rn(xv0[nt].x, xv0[nt].y);
            const __half2 x1 = __floats2half2_rn(xv1[nt].x, xv1[nt].y);
            const __half2 t0 = __hmax2(__hadd2(x0, s0), zero_h2);
            const __half2 t1 = __hmax2(__hadd2(x1, s1), zero_h2);
            const uint32_t o0 = (uint32_t)m0 * 128u + (uint32_t)((nt ^ sw0) << 4) + 4u * c;
            const uint32_t o1 = o0 + 8u * 128u;   // row m0+8, same swizzle key
            *(uint32_t*)(smem + OFF_T + o0) = *(const uint32_t*)&t0;
            *(uint32_t*)(smem + OFF_T + o1) = *(const uint32_t*)&t1;
        }
        __syncthreads();   // S2: T tile visible

        // prefetch next tile (streaming loads — do not evict x/agg from L2)
        const int nt_tile = tile + GRID;
        if (nt_tile < NTILE) {
            const float4* ep4 = (const float4*)eattr + (size_t)nt_tile * TILE * 16;
#pragma unroll
            for (int q = 0; q < 8; ++q) vr[q] = __ldcs(ep4 + tid + 256 * q);
            idxn = (tid < 128) ? eidx[nt_tile * TILE + tid]
                               : eidx[EE + nt_tile * TILE + (tid - 128)];
        }

        // ---- GEMM2: msg = t @ Wm + bm ----
#pragma unroll
        for (int nt = 0; nt < 8; ++nt) {
            const float2 bv = *(const float2*)(sbm + 8 * nt + 2 * c);
            acc[nt][0] = bv.x; acc[nt][1] = bv.y;
            acc[nt][2] = bv.x; acc[nt][3] = bv.y;
        }
        run_gemm(tB, wmB, w, l, acc);

        // ---- epilogue2 (half2 silu): scatter-add into agg[dst] (L2-resident) ----
        {
            float* p0 = g_agg + (size_t)dst0 * DD + 2 * c;
            float* p1 = g_agg + (size_t)dst1 * DD + 2 * c;
#pragma unroll
            for (int nt = 0; nt < 8; ++nt) {
                const __half2 s0 = silu_h2(__floats2half2_rn(acc[nt][0], acc[nt][1]));
                const __half2 s1 = silu_h2(__floats2half2_rn(acc[nt][2], acc[nt][3]));
                const float2 m01 = __half22float2(s0);
                const float2 m23 = __half22float2(s1);
                asm volatile("red.global.add.v2.f32 [%0], {%1,%2};"
                             :: "l"(p0 + 8 * nt), "f"(m01.x), "f"(m01.y) : "memory");
                asm volatile("red.global.add.v2.f32 [%0], {%1,%2};"
                             :: "l"(p1 + 8 * nt), "f"(m23.x), "f"(m23.y) : "memory");
            }
        }
        // No tail barrier: next iteration's A/idx writes are ordered by S1, and
        // all reads of this tile's A/T/indices completed before S2 / in-registers.
    }
}

// ---------------- kernel 3: per-graph sum / sumsq / count ----------------
__global__ void stats_kernel(const int* __restrict__ n2g) {
    const int lane = threadIdx.x & 31;
    const int wid  = (blockIdx.x * blockDim.x + threadIdx.x) >> 5;
    const int nwarps = (gridDim.x * blockDim.x) >> 5;
    for (int n = wid; n < NN; n += nwarps) {
        const float2 v = *(const float2*)(g_agg + (size_t)n * DD + lane * 2);
        float s = v.x + v.y;
        float q = v.x * v.x + v.y * v.y;
#pragma unroll
        for (int o = 16; o; o >>= 1) {
            s += __shfl_xor_sync(0xffffffffu, s, o);
            q += __shfl_xor_sync(0xffffffffu, q, o);
        }
        if (lane == 0) {
            const int g = n2g[n];
            atomicAdd(&g_sum[g], s);
            atomicAdd(&g_ss[g], q);
            atomicAdd(&g_cnt[g], 1.0f);
        }
    }
}

// ---------------- kernel 4: per-graph mean / rstd ----------------
__global__ void finalize_kernel() {
    const int t = threadIdx.x;
    if (t < GG) {
        const float c = fmaxf(g_cnt[t] * (float)DD, 1.0f);
        const float m = g_sum[t] / c;
        const float var = g_ss[t] / c - m * m;
        g_mean[t] = m;
        g_rstd[t] = rsqrtf(var + 1e-5f);
    }
}

// ---------------- kernel 5: normalize + affine + residual + relu ----------------
__global__ void norm_kernel(const float* __restrict__ x, const int* __restrict__ n2g,
                            const float* __restrict__ gamma, const float* __restrict__ beta,
                            float* __restrict__ out) {
    const float4* x4 = (const float4*)x;
    const float4* a4 = (const float4*)g_agg;
    const float4* g4 = (const float4*)gamma;
    const float4* b4 = (const float4*)beta;
    float4* o4 = (float4*)out;
    const int total = NN * (DD / 4);
    for (int i = blockIdx.x * blockDim.x + threadIdx.x; i < total;
         i += gridDim.x * blockDim.x) {
        const int n = i >> 4, c = i & 15;
        const int g = n2g[n];
        const float m = g_mean[g], r = g_rstd[g];
        const float4 a = a4[i], xv = x4[i], gm = g4[c], bt = b4[c];
        float4 o;
        o.x = fmaxf(fmaf((a.x - m) * r, gm.x, bt.x) + xv.x, 0.0f);
        o.y = fmaxf(fmaf((a.y - m) * r, gm.y, bt.y) + xv.y, 0.0f);
        o.z = fmaxf(fmaf((a.z - m) * r, gm.z, bt.z) + xv.z, 0.0f);
        o.w = fmaxf(fmaf((a.w - m) * r, gm.w, bt.w) + xv.w, 0.0f);
        __stcs(o4 + i, o);   // streamed: out is never re-read
    }
}

// ---------------- launch ----------------
// Inputs: 0:x 1:edge_index 2:edge_attr 3:node2graph
//   4..10: conv1/norm1 (dead branch)  11:We2 12:be2 13:Wm2 14:bm2 15:eps2 16:gamma2 17:beta2
extern "C" void kernel_launch(void* const* d_in, const int* in_sizes, int n_in,
                              void* d_out, int out_size) {
    const float* x      = (const float*)d_in[0];
    const int*   eidx   = (const int*)d_in[1];
    const float* eattr  = (const float*)d_in[2];
    const int*   n2g    = (const int*)d_in[3];
    const float* We2    = (const float*)d_in[11];
    const float* be2    = (const float*)d_in[12];
    const float* Wm2    = (const float*)d_in[13];
    const float* bm2    = (const float*)d_in[14];
    const float* eps2   = (const float*)d_in[15];
    const float* gamma2 = (const float*)d_in[16];
    const float* beta2  = (const float*)d_in[17];
    float* out = (float*)d_out;

    cudaFuncSetAttribute(edge_kernel,
                         cudaFuncAttributeMaxDynamicSharedMemorySize, SMEM_BYTES);

    init_kernel<<<2048, 256>>>(x, eps2);
    // two no-ops shift the ncu -s slot (which has landed on sequence position 4
    // every round) onto edge_kernel, so we finally get its profile
    nop_kernel<<<1, 32>>>();
    nop_kernel<<<1, 32>>>();
    edge_kernel<<<GRID, 256, SMEM_BYTES>>>(x, eidx, eattr, We2, be2, Wm2, bm2);
    stats_kernel<<<1024, 256>>>(n2g);
    finalize_kernel<<<1, 512>>>();
    norm_kernel<<<2048, 256>>>(x, n2g, gamma2, beta2, out);
}